// round 1
// baseline (speedup 1.0000x reference)
#include <cuda_runtime.h>
#include <cuda_bf16.h>

// ---------------------------------------------------------------------------
// Problem constants
//   B=8, NT=32, NO=8, C=512, VD=1024, RD=300, H=4
//   No = 512, Nr = 2048
// ---------------------------------------------------------------------------

#define B_  8
#define NT_ 32
#define NO_ 8
#define C_  512
#define VD_ 1024
#define RD_ 300
#define H_  4
#define DH_ 128            // C/H
#define NoN 512            // No
#define NrN 2048           // Nr
#define SEGS 2048          // b*NT*NO
#define TOK  16384         // b*Nr = total r tokens
#define ROWS_O 4096        // b*No
#define OUT_ROWS 4096      // b*NT*2*NO

// ---------------------------------------------------------------------------
// Scratch (device globals; no allocation allowed)
// ---------------------------------------------------------------------------
__device__ float g_T1 [ROWS_O * 1024];   // xo @ Wo1            (4096,1024)
__device__ float g_H1o[ROWS_O * 1024];   // relu(Ah@T1 + T1)    (4096,1024)
__device__ float g_T2 [ROWS_O * 512];    // H1o @ Wo2           (4096,512)
__device__ float g_Go [ROWS_O * 512];    // relu(Ah@T2 + T2)    (4096,512)
__device__ float g_T3 [TOK * 1024];      // xr @ Wr1            (16384,1024)
__device__ float g_H1r[TOK * 1024];      // relu(Ah@T3 + T3)    (16384,1024)
__device__ float g_T4 [TOK * 512];       // H1r @ Wr2           (16384,512)
__device__ float g_Gr [TOK * 512];       // relu(Ah@T4 + T4)    (16384,512)
__device__ float g_Q  [TOK * 512];
__device__ float g_K  [TOK * 512];
__device__ float g_V  [TOK * 512];
__device__ float g_OmA[SEGS * 512];      // mean attention out, a-path
__device__ float g_OmO[SEGS * 512];      // mean attention out, o-path
__device__ float g_a  [SEGS * 512];      // OmA @ Wp + bp
__device__ float g_o  [SEGS * 512];      // OmO @ Wp + bp
__device__ float g_cat[OUT_ROWS * 1024]; // concat, final GEMM input

// ---------------------------------------------------------------------------
// General batched SGEMM: C = op( A(M,K) @ B(K,N) [+ bias] [+ X] ), op = relu?
// 128x128 tile, BK=8, 256 threads, 8x8 per-thread microtile.
// Per grid.z batch: A += z*sA, B += z*sB, C += z*sC, X += z*sC.
// "X" implements the (A+I)@T = A@T + T self-loop fusion.
// ---------------------------------------------------------------------------
#define BM 128
#define BN 128
#define BK 8
#define TM 8
#define TN 8

__global__ __launch_bounds__(256, 2)
void sgemm_kernel(const float* __restrict__ A, const float* __restrict__ Bm,
                  const float* __restrict__ bias, const float* __restrict__ Xadd,
                  float* __restrict__ Cm,
                  int M, int N, int K,
                  long sA, long sB, long sC, int relu)
{
    const int bz = blockIdx.z;
    A  += (long)bz * sA;
    Bm += (long)bz * sB;
    Cm += (long)bz * sC;
    const float* X = Xadd ? (Xadd + (long)bz * sC) : nullptr;

    __shared__ float As[BK][BM];
    __shared__ float Bs[BK][BN];

    const int tid  = threadIdx.x;          // 0..255
    const int row0 = blockIdx.y * BM;
    const int col0 = blockIdx.x * BN;

    const int trow = (tid >> 4) * TM;      // 0..120
    const int tcol = (tid & 15) * TN;      // 0..120

    // A tile loader: row = tid/2 (0..127), k = (tid&1)*4 + l  (coalesced in K)
    const int aRow = tid >> 1;
    const int aK   = (tid & 1) * 4;
    // B tile loader: k = tid/32 (0..7), col = (tid&31)*4 + l  (coalesced in N)
    const int bK   = tid >> 5;
    const int bCol = (tid & 31) * 4;

    float acc[TM][TN];
    #pragma unroll
    for (int i = 0; i < TM; ++i)
        #pragma unroll
        for (int j = 0; j < TN; ++j) acc[i][j] = 0.f;

    for (int k0 = 0; k0 < K; k0 += BK) {
        // stage A (128 x 8)
        {
            const int gr = row0 + aRow;
            #pragma unroll
            for (int l = 0; l < 4; ++l) {
                const int kk = aK + l;
                const int gk = k0 + kk;
                float v = 0.f;
                if (gr < M && gk < K) v = A[(long)gr * K + gk];
                As[kk][aRow] = v;
            }
        }
        // stage B (8 x 128)
        {
            const int gk = k0 + bK;
            #pragma unroll
            for (int l = 0; l < 4; ++l) {
                const int gc = col0 + bCol + l;
                float v = 0.f;
                if (gk < K && gc < N) v = Bm[(long)gk * N + gc];
                Bs[bK][bCol + l] = v;
            }
        }
        __syncthreads();

        #pragma unroll
        for (int kk = 0; kk < BK; ++kk) {
            float ar[TM], br[TN];
            #pragma unroll
            for (int i = 0; i < TM; ++i) ar[i] = As[kk][trow + i];
            #pragma unroll
            for (int j = 0; j < TN; ++j) br[j] = Bs[kk][tcol + j];
            #pragma unroll
            for (int i = 0; i < TM; ++i)
                #pragma unroll
                for (int j = 0; j < TN; ++j)
                    acc[i][j] = fmaf(ar[i], br[j], acc[i][j]);
        }
        __syncthreads();
    }

    // epilogue
    #pragma unroll
    for (int i = 0; i < TM; ++i) {
        const int gr = row0 + trow + i;
        if (gr >= M) continue;
        #pragma unroll
        for (int j = 0; j < TN; ++j) {
            const int gc = col0 + tcol + j;
            if (gc >= N) continue;
            float v = acc[i][j];
            if (bias) v += bias[gc];
            if (X)    v += X[(long)gr * N + gc];
            if (relu) v = fmaxf(v, 0.f);
            Cm[(long)gr * N + gc] = v;
        }
    }
}

// ---------------------------------------------------------------------------
// Segmented MHA (S=8, H=4, dh=128) producing mean-over-queries output.
// One block per (seg, head); 128 threads.
// path=0: token g = s*8 + i               (seg_a)
// path=1: t=s>>3, j=s&7 ; g = t*64+i*8+j  (seg_o, the swapaxes gather)
// ---------------------------------------------------------------------------
__global__ __launch_bounds__(128)
void attn_mean_kernel(const float* __restrict__ Q, const float* __restrict__ Kt,
                      const float* __restrict__ V, float* __restrict__ Om,
                      int path)
{
    const int s   = blockIdx.x;   // 0..2047
    const int h   = blockIdx.y;   // 0..3
    const int tid = threadIdx.x;  // 0..127

    __shared__ float qs[8][DH_ + 1];
    __shared__ float ks[8][DH_ + 1];
    __shared__ float vs[8][DH_ + 1];
    __shared__ float sc[8][9];
    __shared__ float wj[8];

    #pragma unroll
    for (int i = 0; i < 8; ++i) {
        int g;
        if (path == 0) g = s * 8 + i;
        else { const int t = s >> 3, j = s & 7; g = t * 64 + i * 8 + j; }
        const long off = (long)g * C_ + h * DH_ + tid;
        qs[i][tid] = Q[off];
        ks[i][tid] = Kt[off];
        vs[i][tid] = V[off];
    }
    __syncthreads();

    if (tid < 64) {
        const int i = tid >> 3, j = tid & 7;
        float d = 0.f;
        #pragma unroll 16
        for (int k = 0; k < DH_; ++k) d = fmaf(qs[i][k], ks[j][k], d);
        sc[i][j] = d * 0.08838834764831845f;   // 1/sqrt(128)
    }
    __syncthreads();

    if (tid < 8) {
        const int i = tid;
        float m = -1e30f;
        #pragma unroll
        for (int j = 0; j < 8; ++j) m = fmaxf(m, sc[i][j]);
        float e[8], sum = 0.f;
        #pragma unroll
        for (int j = 0; j < 8; ++j) { e[j] = __expf(sc[i][j] - m); sum += e[j]; }
        const float inv = 1.f / sum;
        #pragma unroll
        for (int j = 0; j < 8; ++j) sc[i][j] = e[j] * inv;
    }
    __syncthreads();

    if (tid < 8) {
        const int j = tid;
        float w = 0.f;
        #pragma unroll
        for (int i = 0; i < 8; ++i) w += sc[i][j];
        wj[j] = w * 0.125f;                    // mean over queries
    }
    __syncthreads();

    float o = 0.f;
    #pragma unroll
    for (int j = 0; j < 8; ++j) o = fmaf(wj[j], vs[j][tid], o);
    Om[(long)s * C_ + h * DH_ + tid] = o;
}

// ---------------------------------------------------------------------------
// Build cat = [ [a|o](row) , Go(row) ]  -> (4096, 1024)
// row = t*16 + r ; r<8 -> a[t*8+r], else o[t*8+r-8] ; second half = Go[row]
// ---------------------------------------------------------------------------
__global__ __launch_bounds__(256)
void build_cat_kernel(const float* __restrict__ a, const float* __restrict__ o,
                      const float* __restrict__ Go, float* __restrict__ cat)
{
    const long idx = (long)blockIdx.x * blockDim.x + threadIdx.x;
    if (idx >= (long)OUT_ROWS * 1024) return;
    const int row = (int)(idx >> 10);
    const int c   = (int)(idx & 1023);
    float v;
    if (c < 512) {
        const int t = row >> 4, r = row & 15;
        if (r < 8) v = a[(long)(t * 8 + r) * 512 + c];
        else       v = o[(long)(t * 8 + r - 8) * 512 + c];
    } else {
        v = Go[(long)row * 512 + (c - 512)];
    }
    cat[idx] = v;
}

// ---------------------------------------------------------------------------
// Host: launch sequence (all on default stream; graph-capturable)
// ---------------------------------------------------------------------------
static inline void gemm(const float* A, const float* Bm, const float* bias,
                        const float* X, float* Cm,
                        int M, int N, int K, long sA, long sB, long sC,
                        int nbatch, int relu)
{
    dim3 grid((N + BN - 1) / BN, (M + BM - 1) / BM, nbatch);
    sgemm_kernel<<<grid, 256>>>(A, Bm, bias, X, Cm, M, N, K, sA, sB, sC, relu);
}

extern "C" void kernel_launch(void* const* d_in, const int* in_sizes, int n_in,
                              void* d_out, int out_size)
{
    const float* Ao   = (const float*)d_in[0];   // (8,512,512)
    const float* srco = (const float*)d_in[1];   // (8,1,1,512,1024) == (4096,1024)
    const float* Ar   = (const float*)d_in[2];   // (8,2048,2048)
    const float* srcr = (const float*)d_in[3];   // (8,1,1,2048,300) == (16384,300)
    const float* Wo1  = (const float*)d_in[4];   // (1024,1024)
    const float* Wo2  = (const float*)d_in[5];   // (1024,512)
    const float* Wr1  = (const float*)d_in[6];   // (300,1024)
    const float* Wr2  = (const float*)d_in[7];   // (1024,512)
    const float* Wq   = (const float*)d_in[8];
    const float* bq   = (const float*)d_in[9];
    const float* Wk   = (const float*)d_in[10];
    const float* bk   = (const float*)d_in[11];
    const float* Wv   = (const float*)d_in[12];
    const float* bv   = (const float*)d_in[13];
    const float* Wp   = (const float*)d_in[14];
    const float* bp   = (const float*)d_in[15];
    const float* We   = (const float*)d_in[16];  // (1024,512)
    const float* be   = (const float*)d_in[17];
    float* out = (float*)d_out;                  // (4096,512)

    float *T1, *H1o, *T2, *Go, *T3, *H1r, *T4, *Gr, *Q, *K, *V;
    float *OmA, *OmO, *a, *o, *cat;
    cudaGetSymbolAddress((void**)&T1,  g_T1);
    cudaGetSymbolAddress((void**)&H1o, g_H1o);
    cudaGetSymbolAddress((void**)&T2,  g_T2);
    cudaGetSymbolAddress((void**)&Go,  g_Go);
    cudaGetSymbolAddress((void**)&T3,  g_T3);
    cudaGetSymbolAddress((void**)&H1r, g_H1r);
    cudaGetSymbolAddress((void**)&T4,  g_T4);
    cudaGetSymbolAddress((void**)&Gr,  g_Gr);
    cudaGetSymbolAddress((void**)&Q,   g_Q);
    cudaGetSymbolAddress((void**)&K,   g_K);
    cudaGetSymbolAddress((void**)&V,   g_V);
    cudaGetSymbolAddress((void**)&OmA, g_OmA);
    cudaGetSymbolAddress((void**)&OmO, g_OmO);
    cudaGetSymbolAddress((void**)&a,   g_a);
    cudaGetSymbolAddress((void**)&o,   g_o);
    cudaGetSymbolAddress((void**)&cat, g_cat);

    // ---- GCN on "o" graph ----
    gemm(srco, Wo1, nullptr, nullptr, T1, ROWS_O, 1024, VD_, 0, 0, 0, 1, 0);
    gemm(Ao, T1, nullptr, T1, H1o, NoN, 1024, NoN,
         (long)NoN * NoN, (long)NoN * 1024, (long)NoN * 1024, B_, 1);
    gemm(H1o, Wo2, nullptr, nullptr, T2, ROWS_O, 512, 1024, 0, 0, 0, 1, 0);
    gemm(Ao, T2, nullptr, T2, Go, NoN, 512, NoN,
         (long)NoN * NoN, (long)NoN * 512, (long)NoN * 512, B_, 1);

    // ---- GCN on "r" graph ----
    gemm(srcr, Wr1, nullptr, nullptr, T3, TOK, 1024, RD_, 0, 0, 0, 1, 0);
    gemm(Ar, T3, nullptr, T3, H1r, NrN, 1024, NrN,
         (long)NrN * NrN, (long)NrN * 1024, (long)NrN * 1024, B_, 1);
    gemm(H1r, Wr2, nullptr, nullptr, T4, TOK, 512, 1024, 0, 0, 0, 1, 0);
    gemm(Ar, T4, nullptr, T4, Gr, NrN, 512, NrN,
         (long)NrN * NrN, (long)NrN * 512, (long)NrN * 512, B_, 1);

    // ---- QKV projections (shared by both MHA paths; o-path is a permutation) ----
    gemm(Gr, Wq, bq, nullptr, Q, TOK, 512, 512, 0, 0, 0, 1, 0);
    gemm(Gr, Wk, bk, nullptr, K, TOK, 512, 512, 0, 0, 0, 1, 0);
    gemm(Gr, Wv, bv, nullptr, V, TOK, 512, 512, 0, 0, 0, 1, 0);

    // ---- attention (mean over queries fused) ----
    {
        dim3 grid(SEGS, H_);
        attn_mean_kernel<<<grid, 128>>>(Q, K, V, OmA, 0);
        attn_mean_kernel<<<grid, 128>>>(Q, K, V, OmO, 1);
    }

    // ---- output projection of mean (mean commutes with linear Wp) ----
    gemm(OmA, Wp, bp, nullptr, a, SEGS, 512, 512, 0, 0, 0, 1, 0);
    gemm(OmO, Wp, bp, nullptr, o, SEGS, 512, 512, 0, 0, 0, 1, 0);

    // ---- concat + final projection ----
    {
        const long total = (long)OUT_ROWS * 1024;
        build_cat_kernel<<<(int)((total + 255) / 256), 256>>>(a, o, Go, cat);
    }
    gemm(cat, We, be, nullptr, out, OUT_ROWS, 512, 1024, 0, 0, 0, 1, 0);
}

// round 7
// speedup vs baseline: 3.3092x; 3.3092x over previous
#include <cuda_runtime.h>
#include <cuda_bf16.h>
#include <cstdint>

// ---------------------------------------------------------------------------
// Problem constants: B=8, NT=32, NO=8, C=512, VD=1024, RD=300, H=4
// ---------------------------------------------------------------------------
#define B_  8
#define C_  512
#define VD_ 1024
#define RD_ 300
#define H_  4
#define DH_ 128
#define NoN 512
#define NrN 2048
#define SEGS 2048
#define TOK  16384
#define ROWS_O 4096
#define OUT_ROWS 4096

// ---------------------------------------------------------------------------
// Scratch (no allocation allowed)
// ---------------------------------------------------------------------------
__device__ float g_T1 [ROWS_O * 1024];
__device__ float g_H1o[ROWS_O * 1024];
__device__ float g_T2 [ROWS_O * 512];
__device__ float g_Go [ROWS_O * 512];
__device__ float g_Z  [TOK * 300];        // (Ar@xr + xr)
__device__ float g_H1r[TOK * 1024];
__device__ float g_T4 [TOK * 512];
__device__ float g_Gr [TOK * 512];
__device__ float g_Q  [TOK * 512];
__device__ float g_K  [TOK * 512];
__device__ float g_V  [TOK * 512];
__device__ float g_OmA[SEGS * 512];
__device__ float g_OmO[SEGS * 512];
__device__ float g_a  [SEGS * 512];
__device__ float g_o  [SEGS * 512];
__device__ float g_cat[OUT_ROWS * 1024];

// ---------------------------------------------------------------------------
// SMEM layout per stage (all offsets in bytes):
//   As hi: 128 rows x 80B pitch (32 bf16 used)   -> 10240
//   As lo: 10240
//   Bs hi: 32 k-rows x 272B pitch (128 bf16)     ->  8704
//   Bs lo:  8704
// ---------------------------------------------------------------------------
#define PITCH_A 80
#define PITCH_B 272
#define OFF_AL 10240
#define OFF_BH 20480
#define OFF_BL 29184
#define STAGE_B 37888
#define SMEM_DYN (2 * STAGE_B)   // 75776

__device__ __forceinline__ uint32_t smem_u32(const void* p) {
    uint32_t a;
    asm("{ .reg .u64 t; cvta.to.shared.u64 t, %1; cvt.u32.u64 %0, t; }"
        : "=r"(a) : "l"(p));
    return a;
}
__device__ __forceinline__ void ldsm4(uint32_t* r, uint32_t addr) {
    asm volatile("ldmatrix.sync.aligned.m8n8.x4.shared.b16 {%0,%1,%2,%3}, [%4];"
                 : "=r"(r[0]), "=r"(r[1]), "=r"(r[2]), "=r"(r[3]) : "r"(addr));
}
__device__ __forceinline__ void ldsm2t(uint32_t* r, uint32_t addr) {
    asm volatile("ldmatrix.sync.aligned.m8n8.x2.trans.shared.b16 {%0,%1}, [%2];"
                 : "=r"(r[0]), "=r"(r[1]) : "r"(addr));
}
__device__ __forceinline__ void mma16816(float* d, const uint32_t* a, const uint32_t* b) {
    asm volatile(
        "mma.sync.aligned.m16n8k16.row.col.f32.bf16.bf16.f32 "
        "{%0,%1,%2,%3}, {%4,%5,%6,%7}, {%8,%9}, {%0,%1,%2,%3};"
        : "+f"(d[0]), "+f"(d[1]), "+f"(d[2]), "+f"(d[3])
        : "r"(a[0]), "r"(a[1]), "r"(a[2]), "r"(a[3]), "r"(b[0]), "r"(b[1]));
}
__device__ __forceinline__ void split2(float x, float y, uint32_t& h, uint32_t& l) {
    __nv_bfloat16 hx = __float2bfloat16(x), hy = __float2bfloat16(y);
    __nv_bfloat16 lx = __float2bfloat16(x - __bfloat162float(hx));
    __nv_bfloat16 ly = __float2bfloat16(y - __bfloat162float(hy));
    h = (uint32_t)__bfloat16_as_ushort(hx) | ((uint32_t)__bfloat16_as_ushort(hy) << 16);
    l = (uint32_t)__bfloat16_as_ushort(lx) | ((uint32_t)__bfloat16_as_ushort(ly) << 16);
}

// ---------------------------------------------------------------------------
// HMMA bf16-split GEMM: C = op( A(M,K)@B(K,N) [+bias] [+X] ), op=relu?
// 128x128 CTA tile, BK=32, 256 threads (2x4 warps, 64x32 warp tile),
// double-buffered SMEM, 3 MMAs per fragment pair (hi/lo split).
// M % 128 == 0 required; N,K arbitrary (N % 4 == 0 assumed for vec I/O).
// ---------------------------------------------------------------------------
__global__ __launch_bounds__(256, 1)
void mm_kernel(const float* __restrict__ A, const float* __restrict__ Bm,
               const float* __restrict__ bias, const float* __restrict__ Xadd,
               float* __restrict__ Cm,
               int M, int N, int K, long sA, long sB, long sC, int relu)
{
    extern __shared__ char smem[];
    const uint32_t sbase0 = smem_u32(smem);

    const int bz = blockIdx.z;
    A  += (long)bz * sA;
    Bm += (long)bz * sB;
    Cm += (long)bz * sC;
    const float* X = Xadd ? (Xadd + (long)bz * sC) : nullptr;

    const int tid  = threadIdx.x;
    const int wid  = tid >> 5;
    const int lane = tid & 31;
    const int row0 = blockIdx.y * 128;
    const int col0 = blockIdx.x * 128;

    const int wm = wid >> 2;          // 0..1  -> row offset wm*64
    const int wn = wid & 3;           // 0..3  -> col offset wn*32

    // staging thread mapping
    const int ar  = tid >> 3;         // 0..31 (A row quarter base)
    const int akq = (tid & 7) * 4;    // 0..28 (A k within chunk)
    const int bk  = tid >> 5;         // 0..7  (B k-row base)
    const int bn4 = (tid & 31) * 4;   // 0..124 (B n within tile)

    const float* Ap = A + (long)row0 * K;
    const bool colFast = (col0 + 128 <= N);

    float acc[4][4][4];
    #pragma unroll
    for (int mt = 0; mt < 4; ++mt)
        #pragma unroll
        for (int nt = 0; nt < 4; ++nt)
            #pragma unroll
            for (int e = 0; e < 4; ++e) acc[mt][nt][e] = 0.f;

    const int nch = (K + 31) >> 5;
    float4 pa[4], pb[4];

    auto loadChunk = [&](int c) {
        const int k0 = c << 5;
        if (k0 + 32 <= K) {
            #pragma unroll
            for (int p = 0; p < 4; ++p)
                pa[p] = *(const float4*)(Ap + (long)(ar + 32 * p) * K + k0 + akq);
        } else {
            #pragma unroll
            for (int p = 0; p < 4; ++p) {
                float v[4];
                #pragma unroll
                for (int j = 0; j < 4; ++j) {
                    const int gk = k0 + akq + j;
                    v[j] = (gk < K) ? Ap[(long)(ar + 32 * p) * K + gk] : 0.f;
                }
                pa[p] = make_float4(v[0], v[1], v[2], v[3]);
            }
        }
        if (k0 + 32 <= K && colFast) {
            const float* Bc = Bm + (long)k0 * N + col0 + bn4;
            #pragma unroll
            for (int p = 0; p < 4; ++p)
                pb[p] = *(const float4*)(Bc + (long)(bk + 8 * p) * N);
        } else {
            #pragma unroll
            for (int p = 0; p < 4; ++p) {
                const int gk = k0 + bk + 8 * p;
                float v[4];
                #pragma unroll
                for (int j = 0; j < 4; ++j) {
                    const int gc = col0 + bn4 + j;
                    v[j] = (gk < K && gc < N) ? Bm[(long)gk * N + gc] : 0.f;
                }
                pb[p] = make_float4(v[0], v[1], v[2], v[3]);
            }
        }
    };

    auto stsChunk = [&](int s) {
        char* st = smem + s * STAGE_B;
        #pragma unroll
        for (int p = 0; p < 4; ++p) {
            uint32_t h01, h23, l01, l23;
            split2(pa[p].x, pa[p].y, h01, l01);
            split2(pa[p].z, pa[p].w, h23, l23);
            const int off = (ar + 32 * p) * PITCH_A + akq * 2;
            *(uint32_t*)(st + off)              = h01;
            *(uint32_t*)(st + off + 4)          = h23;
            *(uint32_t*)(st + OFF_AL + off)     = l01;
            *(uint32_t*)(st + OFF_AL + off + 4) = l23;
        }
        #pragma unroll
        for (int p = 0; p < 4; ++p) {
            uint32_t h01, h23, l01, l23;
            split2(pb[p].x, pb[p].y, h01, l01);
            split2(pb[p].z, pb[p].w, h23, l23);
            const int off = (bk + 8 * p) * PITCH_B + bn4 * 2;
            *(uint32_t*)(st + OFF_BH + off)     = h01;
            *(uint32_t*)(st + OFF_BH + off + 4) = h23;
            *(uint32_t*)(st + OFF_BL + off)     = l01;
            *(uint32_t*)(st + OFF_BL + off + 4) = l23;
        }
    };

    auto computeChunk = [&](int s) {
        const uint32_t sb = sbase0 + s * STAGE_B;
        #pragma unroll
        for (int kb = 0; kb < 32; kb += 16) {
            uint32_t ah[4][4], al[4][4], bh[4][2], bl[4][2];
            #pragma unroll
            for (int mt = 0; mt < 4; ++mt) {
                const uint32_t arow = wm * 64 + mt * 16 + (lane & 15);
                const uint32_t aoff = sb + arow * PITCH_A + (kb + ((lane >> 4) * 8)) * 2;
                ldsm4(ah[mt], aoff);
                ldsm4(al[mt], aoff + OFF_AL);
            }
            #pragma unroll
            for (int nt = 0; nt < 4; ++nt) {
                const uint32_t krow = kb + (lane & 7) + (((lane >> 3) & 1) * 8);
                const uint32_t boff = sb + OFF_BH + krow * PITCH_B + (wn * 32 + nt * 8) * 2;
                ldsm2t(bh[nt], boff);
                ldsm2t(bl[nt], boff + (OFF_BL - OFF_BH));
            }
            #pragma unroll
            for (int mt = 0; mt < 4; ++mt)
                #pragma unroll
                for (int nt = 0; nt < 4; ++nt) {
                    mma16816(acc[mt][nt], ah[mt], bh[nt]);
                    mma16816(acc[mt][nt], al[mt], bh[nt]);
                    mma16816(acc[mt][nt], ah[mt], bl[nt]);
                }
        }
    };

    loadChunk(0);
    stsChunk(0);
    __syncthreads();

    for (int c = 0; c < nch; ++c) {
        if (c + 1 < nch) loadChunk(c + 1);
        computeChunk(c & 1);
        if (c + 1 < nch) stsChunk((c + 1) & 1);
        __syncthreads();
    }

    // epilogue: registers -> global with bias / +X / relu
    #pragma unroll
    for (int mt = 0; mt < 4; ++mt) {
        #pragma unroll
        for (int nt = 0; nt < 4; ++nt) {
            const int col = col0 + wn * 32 + nt * 8 + (lane & 3) * 2;
            if (col >= N) continue;
            #pragma unroll
            for (int half = 0; half < 2; ++half) {
                const int row = row0 + wm * 64 + mt * 16 + (lane >> 2) + half * 8;
                float2 v = make_float2(acc[mt][nt][half * 2], acc[mt][nt][half * 2 + 1]);
                if (bias) {
                    const float2 bv = *(const float2*)(bias + col);
                    v.x += bv.x; v.y += bv.y;
                }
                if (X) {
                    const float2 xv = *(const float2*)(X + (long)row * N + col);
                    v.x += xv.x; v.y += xv.y;
                }
                if (relu) { v.x = fmaxf(v.x, 0.f); v.y = fmaxf(v.y, 0.f); }
                *(float2*)(Cm + (long)row * N + col) = v;
            }
        }
    }
}

// ---------------------------------------------------------------------------
// Segmented MHA (S=8, H=4, dh=128) with mean-over-queries fused.
// ---------------------------------------------------------------------------
__global__ __launch_bounds__(128)
void attn_mean_kernel(const float* __restrict__ Q, const float* __restrict__ Kt,
                      const float* __restrict__ V, float* __restrict__ Om, int path)
{
    const int s = blockIdx.x, h = blockIdx.y, tid = threadIdx.x;
    __shared__ float qs[8][DH_ + 1], ks[8][DH_ + 1], vs[8][DH_ + 1];
    __shared__ float sc[8][9], wj[8];

    #pragma unroll
    for (int i = 0; i < 8; ++i) {
        int g;
        if (path == 0) g = s * 8 + i;
        else { const int t = s >> 3, j = s & 7; g = t * 64 + i * 8 + j; }
        const long off = (long)g * C_ + h * DH_ + tid;
        qs[i][tid] = Q[off]; ks[i][tid] = Kt[off]; vs[i][tid] = V[off];
    }
    __syncthreads();

    if (tid < 64) {
        const int i = tid >> 3, j = tid & 7;
        float d = 0.f;
        #pragma unroll 16
        for (int k = 0; k < DH_; ++k) d = fmaf(qs[i][k], ks[j][k], d);
        sc[i][j] = d * 0.08838834764831845f;
    }
    __syncthreads();
    if (tid < 8) {
        const int i = tid;
        float m = -1e30f;
        #pragma unroll
        for (int j = 0; j < 8; ++j) m = fmaxf(m, sc[i][j]);
        float e[8], sum = 0.f;
        #pragma unroll
        for (int j = 0; j < 8; ++j) { e[j] = __expf(sc[i][j] - m); sum += e[j]; }
        const float inv = 1.f / sum;
        #pragma unroll
        for (int j = 0; j < 8; ++j) sc[i][j] = e[j] * inv;
    }
    __syncthreads();
    if (tid < 8) {
        const int j = tid;
        float w = 0.f;
        #pragma unroll
        for (int i = 0; i < 8; ++i) w += sc[i][j];
        wj[j] = w * 0.125f;
    }
    __syncthreads();
    float o = 0.f;
    #pragma unroll
    for (int j = 0; j < 8; ++j) o = fmaf(wj[j], vs[j][tid], o);
    Om[(long)s * C_ + h * DH_ + tid] = o;
}

// ---------------------------------------------------------------------------
// Concat builder
// ---------------------------------------------------------------------------
__global__ __launch_bounds__(256)
void build_cat_kernel(const float* __restrict__ a, const float* __restrict__ o,
                      const float* __restrict__ Go, float* __restrict__ cat)
{
    const long idx = (long)blockIdx.x * blockDim.x + threadIdx.x;
    if (idx >= (long)OUT_ROWS * 1024) return;
    const int row = (int)(idx >> 10);
    const int c = (int)(idx & 1023);
    float v;
    if (c < 512) {
        const int t = row >> 4, r = row & 15;
        v = (r < 8) ? a[(long)(t * 8 + r) * 512 + c] : o[(long)(t * 8 + r - 8) * 512 + c];
    } else {
        v = Go[(long)row * 512 + (c - 512)];
    }
    cat[idx] = v;
}

// ---------------------------------------------------------------------------
// Host
// ---------------------------------------------------------------------------
static inline void mm(const float* A, const float* Bm, const float* bias,
                      const float* X, float* Cm, int M, int N, int K,
                      long sA, long sB, long sC, int nb, int relu)
{
    dim3 grid((N + 127) / 128, M / 128, nb);
    mm_kernel<<<grid, 256, SMEM_DYN>>>(A, Bm, bias, X, Cm, M, N, K, sA, sB, sC, relu);
}

extern "C" void kernel_launch(void* const* d_in, const int* in_sizes, int n_in,
                              void* d_out, int out_size)
{
    const float* Ao   = (const float*)d_in[0];
    const float* srco = (const float*)d_in[1];
    const float* Ar   = (const float*)d_in[2];
    const float* srcr = (const float*)d_in[3];
    const float* Wo1  = (const float*)d_in[4];
    const float* Wo2  = (const float*)d_in[5];
    const float* Wr1  = (const float*)d_in[6];
    const float* Wr2  = (const float*)d_in[7];
    const float* Wq   = (const float*)d_in[8];
    const float* bq   = (const float*)d_in[9];
    const float* Wk   = (const float*)d_in[10];
    const float* bk   = (const float*)d_in[11];
    const float* Wv   = (const float*)d_in[12];
    const float* bv   = (const float*)d_in[13];
    const float* Wp   = (const float*)d_in[14];
    const float* bp   = (const float*)d_in[15];
    const float* We   = (const float*)d_in[16];
    const float* be   = (const float*)d_in[17];
    float* out = (float*)d_out;

    cudaFuncSetAttribute(mm_kernel, cudaFuncAttributeMaxDynamicSharedMemorySize, SMEM_DYN);

    float *T1, *H1o, *T2, *Go, *Z, *H1r, *T4, *Gr, *Q, *K, *V, *OmA, *OmO, *a, *o, *cat;
    cudaGetSymbolAddress((void**)&T1, g_T1);
    cudaGetSymbolAddress((void**)&H1o, g_H1o);
    cudaGetSymbolAddress((void**)&T2, g_T2);
    cudaGetSymbolAddress((void**)&Go, g_Go);
    cudaGetSymbolAddress((void**)&Z, g_Z);
    cudaGetSymbolAddress((void**)&H1r, g_H1r);
    cudaGetSymbolAddress((void**)&T4, g_T4);
    cudaGetSymbolAddress((void**)&Gr, g_Gr);
    cudaGetSymbolAddress((void**)&Q, g_Q);
    cudaGetSymbolAddress((void**)&K, g_K);
    cudaGetSymbolAddress((void**)&V, g_V);
    cudaGetSymbolAddress((void**)&OmA, g_OmA);
    cudaGetSymbolAddress((void**)&OmO, g_OmO);
    cudaGetSymbolAddress((void**)&a, g_a);
    cudaGetSymbolAddress((void**)&o, g_o);
    cudaGetSymbolAddress((void**)&cat, g_cat);

    // ---- GCN "o" ----
    mm(srco, Wo1, nullptr, nullptr, T1, ROWS_O, 1024, VD_, 0, 0, 0, 1, 0);
    mm(Ao, T1, nullptr, T1, H1o, NoN, 1024, NoN,
       (long)NoN * NoN, (long)NoN * 1024, (long)NoN * 1024, B_, 1);
    mm(H1o, Wo2, nullptr, nullptr, T2, ROWS_O, 512, 1024, 0, 0, 0, 1, 0);
    mm(Ao, T2, nullptr, T2, Go, NoN, 512, NoN,
       (long)NoN * NoN, (long)NoN * 512, (long)NoN * 512, B_, 1);

    // ---- GCN "r" (layer1 reassociated: relu(((Ar@x)+x)@Wr1)) ----
    mm(Ar, srcr, nullptr, srcr, Z, NrN, RD_, NrN,
       (long)NrN * NrN, (long)NrN * RD_, (long)NrN * RD_, B_, 0);
    mm(Z, Wr1, nullptr, nullptr, H1r, TOK, 1024, RD_, 0, 0, 0, 1, 1);
    mm(H1r, Wr2, nullptr, nullptr, T4, TOK, 512, 1024, 0, 0, 0, 1, 0);
    mm(Ar, T4, nullptr, T4, Gr, NrN, 512, NrN,
       (long)NrN * NrN, (long)NrN * 512, (long)NrN * 512, B_, 1);

    // ---- QKV ----
    mm(Gr, Wq, bq, nullptr, Q, TOK, 512, 512, 0, 0, 0, 1, 0);
    mm(Gr, Wk, bk, nullptr, K, TOK, 512, 512, 0, 0, 0, 1, 0);
    mm(Gr, Wv, bv, nullptr, V, TOK, 512, 512, 0, 0, 0, 1, 0);

    // ---- attention ----
    {
        dim3 grid(SEGS, H_);
        attn_mean_kernel<<<grid, 128>>>(Q, K, V, OmA, 0);
        attn_mean_kernel<<<grid, 128>>>(Q, K, V, OmO, 1);
    }

    // ---- mean @ Wp (mean commutes with linear) ----
    mm(OmA, Wp, bp, nullptr, a, SEGS, 512, 512, 0, 0, 0, 1, 0);
    mm(OmO, Wp, bp, nullptr, o, SEGS, 512, 512, 0, 0, 0, 1, 0);

    // ---- concat + final ----
    {
        const long total = (long)OUT_ROWS * 1024;
        build_cat_kernel<<<(int)((total + 255) / 256), 256>>>(a, o, Go, cat);
    }
    mm(cat, We, be, nullptr, out, OUT_ROWS, 512, 1024, 0, 0, 0, 1, 0);
}

// round 8
// speedup vs baseline: 3.6127x; 1.0917x over previous
#include <cuda_runtime.h>
#include <cuda_bf16.h>
#include <cstdint>

// ---------------------------------------------------------------------------
// Problem constants: B=8, NT=32, NO=8, C=512, VD=1024, RD=300, H=4
// ---------------------------------------------------------------------------
#define B_  8
#define C_  512
#define VD_ 1024
#define RD_ 300
#define H_  4
#define DH_ 128
#define NoN 512
#define NrN 2048
#define SEGS 2048
#define TOK  16384
#define ROWS_O 4096
#define OUT_ROWS 4096

// ---------------------------------------------------------------------------
// fp32 scratch
// ---------------------------------------------------------------------------
__device__ float g_T1 [ROWS_O * 1024];
__device__ float g_T2 [ROWS_O * 512];
__device__ float g_T4 [TOK * 512];
__device__ float g_Go [ROWS_O * 512];
__device__ float g_QKV[TOK * 1536];
__device__ float g_ao [4096 * 512];
__device__ float g_bqkv[1536];

// bf16 hi/lo plane scratch (operands of tensor-core GEMMs)
__device__ __nv_bfloat16 pAo_h [8*512*512],    pAo_l [8*512*512];
__device__ __nv_bfloat16 pAr_h [8*2048*2048],  pAr_l [8*2048*2048];
__device__ __nv_bfloat16 pSo_h [4096*1024],    pSo_l [4096*1024];
__device__ __nv_bfloat16 pSr_h [16384*304],    pSr_l [16384*304];   // padded ld=304
__device__ __nv_bfloat16 pWo1_h[1024*1024],    pWo1_l[1024*1024];
__device__ __nv_bfloat16 pWo2_h[1024*512],     pWo2_l[1024*512];
__device__ __nv_bfloat16 pWr1_h[300*1024],     pWr1_l[300*1024];
__device__ __nv_bfloat16 pWr2_h[1024*512],     pWr2_l[1024*512];
__device__ __nv_bfloat16 pWqkv_h[512*1536],    pWqkv_l[512*1536];
__device__ __nv_bfloat16 pWp_h [512*512],      pWp_l [512*512];
__device__ __nv_bfloat16 pWe_h [1024*512],     pWe_l [1024*512];
__device__ __nv_bfloat16 pT1_h [4096*1024],    pT1_l [4096*1024];
__device__ __nv_bfloat16 pH1o_h[4096*1024],    pH1o_l[4096*1024];
__device__ __nv_bfloat16 pT2_h [4096*512],     pT2_l [4096*512];
__device__ __nv_bfloat16 pZ_h  [16384*304],    pZ_l  [16384*304];   // ld=304
__device__ __nv_bfloat16 pH1r_h[16384*1024],   pH1r_l[16384*1024];
__device__ __nv_bfloat16 pT4_h [16384*512],    pT4_l [16384*512];
__device__ __nv_bfloat16 pGr_h [16384*512],    pGr_l [16384*512];
__device__ __nv_bfloat16 pOm_h [4096*512],     pOm_l [4096*512];
__device__ __nv_bfloat16 pCat_h[4096*1024],    pCat_l[4096*1024];

// ---------------------------------------------------------------------------
// helpers
// ---------------------------------------------------------------------------
__device__ __forceinline__ uint32_t smem_u32(const void* p) {
    uint32_t a;
    asm("{ .reg .u64 t; cvta.to.shared.u64 t, %1; cvt.u32.u64 %0, t; }"
        : "=r"(a) : "l"(p));
    return a;
}
__device__ __forceinline__ void cp16(uint32_t dst, const void* src, int sz) {
    asm volatile("cp.async.cg.shared.global [%0], [%1], 16, %2;"
                 :: "r"(dst), "l"(src), "r"(sz));
}
__device__ __forceinline__ void cp_commit() {
    asm volatile("cp.async.commit_group;");
}
__device__ __forceinline__ void cp_wait(int pend) {
    if (pend >= 2)      asm volatile("cp.async.wait_group 2;");
    else if (pend == 1) asm volatile("cp.async.wait_group 1;");
    else                asm volatile("cp.async.wait_group 0;");
}
__device__ __forceinline__ void ldsm4(uint32_t* r, uint32_t addr) {
    asm volatile("ldmatrix.sync.aligned.m8n8.x4.shared.b16 {%0,%1,%2,%3}, [%4];"
                 : "=r"(r[0]), "=r"(r[1]), "=r"(r[2]), "=r"(r[3]) : "r"(addr));
}
__device__ __forceinline__ void ldsm2t(uint32_t* r, uint32_t addr) {
    asm volatile("ldmatrix.sync.aligned.m8n8.x2.trans.shared.b16 {%0,%1}, [%2];"
                 : "=r"(r[0]), "=r"(r[1]) : "r"(addr));
}
__device__ __forceinline__ void mma16816(float* d, const uint32_t* a, const uint32_t* b) {
    asm volatile(
        "mma.sync.aligned.m16n8k16.row.col.f32.bf16.bf16.f32 "
        "{%0,%1,%2,%3}, {%4,%5,%6,%7}, {%8,%9}, {%0,%1,%2,%3};"
        : "+f"(d[0]), "+f"(d[1]), "+f"(d[2]), "+f"(d[3])
        : "r"(a[0]), "r"(a[1]), "r"(a[2]), "r"(a[3]), "r"(b[0]), "r"(b[1]));
}
__device__ __forceinline__ void split1(float x, __nv_bfloat16& h, __nv_bfloat16& l) {
    h = __float2bfloat16(x);
    l = __float2bfloat16(x - __bfloat162float(h));
}

// ---------------------------------------------------------------------------
// SMEM stage layout (bytes): A hi 128x32 bf16 pitch 80 (10240), A lo,
// B hi 32x128 bf16 pitch 272 (8704), B lo.  3 stages.
// ---------------------------------------------------------------------------
#define PITCH_A 80
#define PITCH_B 272
#define OFF_AL 10240
#define OFF_BH 20480
#define OFF_BL 29184
#define STAGE_B 37888
#define NSTAGE 3
#define SMEM_DYN (NSTAGE * STAGE_B)     // 113664

// ---------------------------------------------------------------------------
// HMMA bf16-split GEMM v2: operands are pre-split bf16 planes.
//   C = op( A@B [+bias] [+X] );  outputs: optional fp32 Cf, optional planes Ch/Cl.
// 128x128 CTA tile, BK=32, 256 threads, cp.async 3-stage pipeline.
// M % 128 == 0; N even; lda/ldb multiples of 8.
// ---------------------------------------------------------------------------
__global__ __launch_bounds__(256, 1)
void mm2_kernel(const __nv_bfloat16* __restrict__ Ah, const __nv_bfloat16* __restrict__ Al,
                int lda, long sAp,
                const __nv_bfloat16* __restrict__ Bh, const __nv_bfloat16* __restrict__ Bl,
                int ldb, long sBp,
                const float* __restrict__ bias,
                const float* __restrict__ Xadd, long sX,
                float* __restrict__ Cf, long sCf,
                __nv_bfloat16* __restrict__ Ch, __nv_bfloat16* __restrict__ Cl,
                int ldo, long sCo,
                int M, int N, int K, int relu)
{
    extern __shared__ char smem[];
    const uint32_t sbase = smem_u32(smem);

    const int bz = blockIdx.z;
    Ah += (long)bz * sAp;  Al += (long)bz * sAp;
    Bh += (long)bz * sBp;  Bl += (long)bz * sBp;
    if (Cf) Cf += (long)bz * sCf;
    if (Ch) { Ch += (long)bz * sCo; Cl += (long)bz * sCo; }
    const float* X = Xadd ? (Xadd + (long)bz * sX) : nullptr;

    const int tid  = threadIdx.x;
    const int wid  = tid >> 5;
    const int lane = tid & 31;
    const int row0 = blockIdx.y * 128;
    const int col0 = blockIdx.x * 128;
    const int wm = wid >> 2;
    const int wn = wid & 3;

    float acc[4][4][4];
    #pragma unroll
    for (int mt = 0; mt < 4; ++mt)
        #pragma unroll
        for (int nt = 0; nt < 4; ++nt)
            #pragma unroll
            for (int e = 0; e < 4; ++e) acc[mt][nt][e] = 0.f;

    const int nch = (K + 31) >> 5;

    auto issueStage = [&](int c, int buf) {
        const int k0 = c << 5;
        const uint32_t sb = sbase + buf * STAGE_B;
        // A planes: 512 chunks each (16B), 2 per thread per plane
        #pragma unroll
        for (int i = 0; i < 2; ++i) {
            const int ch  = tid + i * 256;
            const int row = ch >> 2;
            const int o8  = (ch & 3) * 8;
            const int rem = K - (k0 + o8);
            const int sz  = rem >= 8 ? 16 : (rem > 0 ? rem * 2 : 0);
            const long so = (long)(row0 + row) * lda + (sz ? (k0 + o8) : 0);
            const uint32_t d = sb + row * PITCH_A + (ch & 3) * 16;
            cp16(d,          Ah + so, sz);
            cp16(d + OFF_AL, Al + so, sz);
        }
        // B planes: 512 chunks each
        #pragma unroll
        for (int i = 0; i < 2; ++i) {
            const int ch   = tid + i * 256;
            const int krow = ch >> 4;
            const int no8  = (ch & 15) * 8;
            const int remn = N - (col0 + no8);
            int sz = (k0 + krow < K) ? (remn >= 8 ? 16 : (remn > 0 ? remn * 2 : 0)) : 0;
            const long so = sz ? ((long)(k0 + krow) * ldb + col0 + no8) : 0;
            const uint32_t d = sb + OFF_BH + krow * PITCH_B + (ch & 15) * 16;
            cp16(d,                     Bh + so, sz);
            cp16(d + (OFF_BL - OFF_BH), Bl + so, sz);
        }
    };

    auto computeChunk = [&](int buf) {
        const uint32_t sb = sbase + buf * STAGE_B;
        #pragma unroll
        for (int kb = 0; kb < 32; kb += 16) {
            uint32_t ahf[4][4], alf[4][4], bhf[4][2], blf[4][2];
            #pragma unroll
            for (int mt = 0; mt < 4; ++mt) {
                const uint32_t arow = wm * 64 + mt * 16 + (lane & 15);
                const uint32_t aoff = sb + arow * PITCH_A + (kb + ((lane >> 4) * 8)) * 2;
                ldsm4(ahf[mt], aoff);
                ldsm4(alf[mt], aoff + OFF_AL);
            }
            #pragma unroll
            for (int nt = 0; nt < 4; ++nt) {
                const uint32_t krow = kb + (lane & 7) + (((lane >> 3) & 1) * 8);
                const uint32_t boff = sb + OFF_BH + krow * PITCH_B + (wn * 32 + nt * 8) * 2;
                ldsm2t(bhf[nt], boff);
                ldsm2t(blf[nt], boff + (OFF_BL - OFF_BH));
            }
            #pragma unroll
            for (int mt = 0; mt < 4; ++mt)
                #pragma unroll
                for (int nt = 0; nt < 4; ++nt) {
                    mma16816(acc[mt][nt], ahf[mt], bhf[nt]);
                    mma16816(acc[mt][nt], alf[mt], bhf[nt]);
                    mma16816(acc[mt][nt], ahf[mt], blf[nt]);
                }
        }
    };

    // prologue
    #pragma unroll
    for (int s = 0; s < NSTAGE - 1; ++s)
        if (s < nch) { issueStage(s, s); cp_commit(); }

    for (int c = 0; c < nch; ++c) {
        if (c + 2 < nch) { issueStage(c + 2, (c + 2) % NSTAGE); cp_commit(); }
        const int committed = (nch < c + 3) ? nch : (c + 3);
        cp_wait(committed - (c + 1));
        __syncthreads();
        computeChunk(c % NSTAGE);
        __syncthreads();
    }

    // epilogue
    #pragma unroll
    for (int mt = 0; mt < 4; ++mt) {
        #pragma unroll
        for (int nt = 0; nt < 4; ++nt) {
            const int col = col0 + wn * 32 + nt * 8 + (lane & 3) * 2;
            if (col >= N) continue;
            #pragma unroll
            for (int half = 0; half < 2; ++half) {
                const int row = row0 + wm * 64 + mt * 16 + (lane >> 2) + half * 8;
                float2 v = make_float2(acc[mt][nt][half * 2], acc[mt][nt][half * 2 + 1]);
                if (bias) {
                    const float2 bv = *(const float2*)(bias + col);
                    v.x += bv.x; v.y += bv.y;
                }
                if (X) {
                    const float2 xv = *(const float2*)(X + (long)row * N + col);
                    v.x += xv.x; v.y += xv.y;
                }
                if (relu) { v.x = fmaxf(v.x, 0.f); v.y = fmaxf(v.y, 0.f); }
                if (Cf) *(float2*)(Cf + (long)row * N + col) = v;
                if (Ch) {
                    __nv_bfloat16 hx, lx, hy, ly;
                    split1(v.x, hx, lx); split1(v.y, hy, ly);
                    const long o = (long)row * ldo + col;
                    *(uint32_t*)(Ch + o) =
                        (uint32_t)__bfloat16_as_ushort(hx) | ((uint32_t)__bfloat16_as_ushort(hy) << 16);
                    *(uint32_t*)(Cl + o) =
                        (uint32_t)__bfloat16_as_ushort(lx) | ((uint32_t)__bfloat16_as_ushort(ly) << 16);
                }
            }
        }
    }
}

// ---------------------------------------------------------------------------
// fp32 -> bf16 hi/lo plane convert (optionally row-padded output)
// n = rows*cols total elements; cols % 4 == 0.
// ---------------------------------------------------------------------------
__global__ __launch_bounds__(256)
void cvt_kernel(const float* __restrict__ in, __nv_bfloat16* __restrict__ h,
                __nv_bfloat16* __restrict__ l, long n, int cols, int ldo)
{
    const long i = ((long)blockIdx.x * 256 + threadIdx.x) * 4;
    if (i >= n) return;
    const float4 v = *(const float4*)(in + i);
    long o;
    if (cols == ldo) o = i;
    else { const long r = i / cols; o = r * ldo + (int)(i - r * cols); }
    __nv_bfloat16 hh[4], ll[4];
    split1(v.x, hh[0], ll[0]); split1(v.y, hh[1], ll[1]);
    split1(v.z, hh[2], ll[2]); split1(v.w, hh[3], ll[3]);
    *(uint2*)(h + o) = *(uint2*)hh;
    *(uint2*)(l + o) = *(uint2*)ll;
}

// pack Wq|Wk|Wv -> [512][1536] planes, and bq|bk|bv -> fp32[1536]
__global__ __launch_bounds__(256)
void pack_qkv_kernel(const float* __restrict__ Wq, const float* __restrict__ Wk,
                     const float* __restrict__ Wv, const float* __restrict__ bq,
                     const float* __restrict__ bk, const float* __restrict__ bv,
                     __nv_bfloat16* __restrict__ h, __nv_bfloat16* __restrict__ l,
                     float* __restrict__ bias)
{
    const int idx = blockIdx.x * 256 + threadIdx.x;
    if (idx < 512 * 1536) {
        const int k = idx / 1536, n = idx % 1536, sel = n >> 9;
        const float* W = (sel == 0) ? Wq : (sel == 1) ? Wk : Wv;
        const float v = W[k * 512 + (n & 511)];
        __nv_bfloat16 hh, ll; split1(v, hh, ll);
        h[idx] = hh; l[idx] = ll;
    }
    if (idx < 1536) {
        const int sel = idx >> 9;
        const float* bb = (sel == 0) ? bq : (sel == 1) ? bk : bv;
        bias[idx] = bb[idx & 511];
    }
}

// ---------------------------------------------------------------------------
// Segmented MHA (S=8,H=4,dh=128), mean-over-queries fused, QKV packed (ld 1536).
// Writes Om bf16 planes: rows [path*2048 + s].
// ---------------------------------------------------------------------------
__global__ __launch_bounds__(128)
void attn_mean_kernel(const float* __restrict__ QKV,
                      __nv_bfloat16* __restrict__ OmH, __nv_bfloat16* __restrict__ OmL,
                      int path)
{
    const int s = blockIdx.x, h = blockIdx.y, tid = threadIdx.x;
    __shared__ float qs[8][DH_ + 1], ks[8][DH_ + 1], vs[8][DH_ + 1];
    __shared__ float sc[8][9], wj[8];

    #pragma unroll
    for (int i = 0; i < 8; ++i) {
        int g;
        if (path == 0) g = s * 8 + i;
        else { const int t = s >> 3, j = s & 7; g = t * 64 + i * 8 + j; }
        const long off = (long)g * 1536 + h * DH_ + tid;
        qs[i][tid] = QKV[off];
        ks[i][tid] = QKV[off + 512];
        vs[i][tid] = QKV[off + 1024];
    }
    __syncthreads();

    if (tid < 64) {
        const int i = tid >> 3, j = tid & 7;
        float d = 0.f;
        #pragma unroll 16
        for (int k = 0; k < DH_; ++k) d = fmaf(qs[i][k], ks[j][k], d);
        sc[i][j] = d * 0.08838834764831845f;
    }
    __syncthreads();
    if (tid < 8) {
        const int i = tid;
        float m = -1e30f;
        #pragma unroll
        for (int j = 0; j < 8; ++j) m = fmaxf(m, sc[i][j]);
        float e[8], sum = 0.f;
        #pragma unroll
        for (int j = 0; j < 8; ++j) { e[j] = __expf(sc[i][j] - m); sum += e[j]; }
        const float inv = 1.f / sum;
        #pragma unroll
        for (int j = 0; j < 8; ++j) sc[i][j] = e[j] * inv;
    }
    __syncthreads();
    if (tid < 8) {
        const int j = tid;
        float w = 0.f;
        #pragma unroll
        for (int i = 0; i < 8; ++i) w += sc[i][j];
        wj[j] = w * 0.125f;
    }
    __syncthreads();
    float o = 0.f;
    #pragma unroll
    for (int j = 0; j < 8; ++j) o = fmaf(wj[j], vs[j][tid], o);

    const long off = (long)(path * SEGS + s) * 512 + h * DH_ + tid;
    __nv_bfloat16 hh, ll; split1(o, hh, ll);
    OmH[off] = hh; OmL[off] = ll;
}

// ---------------------------------------------------------------------------
// Build cat planes: [ (a|o) rows from g_ao , Go ] -> bf16 planes (4096x1024)
// ---------------------------------------------------------------------------
__global__ __launch_bounds__(256)
void build_cat_kernel(const float* __restrict__ ao, const float* __restrict__ Go,
                      __nv_bfloat16* __restrict__ h, __nv_bfloat16* __restrict__ l)
{
    const long idx = (long)blockIdx.x * 256 + threadIdx.x;
    if (idx >= (long)OUT_ROWS * 1024) return;
    const int row = (int)(idx >> 10);
    const int c = (int)(idx & 1023);
    float v;
    if (c < 512) {
        const int t = row >> 4, r = row & 15;
        const int arow = (r < 8) ? (t * 8 + r) : (SEGS + t * 8 + (r - 8));
        v = ao[(long)arow * 512 + c];
    } else {
        v = Go[(long)row * 512 + (c - 512)];
    }
    __nv_bfloat16 hh, ll; split1(v, hh, ll);
    h[idx] = hh; l[idx] = ll;
}

// ---------------------------------------------------------------------------
// Host
// ---------------------------------------------------------------------------
#define SYM(p, s) cudaGetSymbolAddress((void**)&p, s)

struct Planes { __nv_bfloat16 *h, *l; };

static inline void mm2(Planes A, int lda, long sAp, Planes Bp, int ldb, long sBp,
                       const float* bias, const float* X, long sX,
                       float* Cf, long sCf, Planes Co, int ldo, long sCo,
                       int M, int N, int K, int nb, int relu)
{
    dim3 grid((N + 127) / 128, M / 128, nb);
    mm2_kernel<<<grid, 256, SMEM_DYN>>>(A.h, A.l, lda, sAp, Bp.h, Bp.l, ldb, sBp,
                                        bias, X, sX, Cf, sCf, Co.h, Co.l, ldo, sCo,
                                        M, N, K, relu);
}
static inline void cvt(const float* in, Planes p, long n, int cols, int ldo)
{
    cvt_kernel<<<(int)((n / 4 + 255) / 256), 256>>>(in, p.h, p.l, n, cols, ldo);
}

extern "C" void kernel_launch(void* const* d_in, const int* in_sizes, int n_in,
                              void* d_out, int out_size)
{
    const float* Ao   = (const float*)d_in[0];
    const float* srco = (const float*)d_in[1];
    const float* Ar   = (const float*)d_in[2];
    const float* srcr = (const float*)d_in[3];
    const float* Wo1  = (const float*)d_in[4];
    const float* Wo2  = (const float*)d_in[5];
    const float* Wr1  = (const float*)d_in[6];
    const float* Wr2  = (const float*)d_in[7];
    const float* Wq   = (const float*)d_in[8];
    const float* bq   = (const float*)d_in[9];
    const float* Wk   = (const float*)d_in[10];
    const float* bk   = (const float*)d_in[11];
    const float* Wv   = (const float*)d_in[12];
    const float* bv   = (const float*)d_in[13];
    const float* Wp   = (const float*)d_in[14];
    const float* bp   = (const float*)d_in[15];
    const float* We   = (const float*)d_in[16];
    const float* be   = (const float*)d_in[17];
    float* out = (float*)d_out;

    cudaFuncSetAttribute(mm2_kernel, cudaFuncAttributeMaxDynamicSharedMemorySize, SMEM_DYN);

    float *T1, *T2, *T4, *Go, *QKV, *ao, *bqkv;
    SYM(T1, g_T1); SYM(T2, g_T2); SYM(T4, g_T4); SYM(Go, g_Go);
    SYM(QKV, g_QKV); SYM(ao, g_ao); SYM(bqkv, g_bqkv);

    Planes PAo, PAr, PSo, PSr, PWo1, PWo2, PWr1, PWr2, PWqkv, PWp, PWe;
    Planes PT1, PH1o, PT2, PZ, PH1r, PT4, PGr, POm, PCat;
    SYM(PAo.h, pAo_h);   SYM(PAo.l, pAo_l);
    SYM(PAr.h, pAr_h);   SYM(PAr.l, pAr_l);
    SYM(PSo.h, pSo_h);   SYM(PSo.l, pSo_l);
    SYM(PSr.h, pSr_h);   SYM(PSr.l, pSr_l);
    SYM(PWo1.h, pWo1_h); SYM(PWo1.l, pWo1_l);
    SYM(PWo2.h, pWo2_h); SYM(PWo2.l, pWo2_l);
    SYM(PWr1.h, pWr1_h); SYM(PWr1.l, pWr1_l);
    SYM(PWr2.h, pWr2_h); SYM(PWr2.l, pWr2_l);
    SYM(PWqkv.h, pWqkv_h); SYM(PWqkv.l, pWqkv_l);
    SYM(PWp.h, pWp_h);   SYM(PWp.l, pWp_l);
    SYM(PWe.h, pWe_h);   SYM(PWe.l, pWe_l);
    SYM(PT1.h, pT1_h);   SYM(PT1.l, pT1_l);
    SYM(PH1o.h, pH1o_h); SYM(PH1o.l, pH1o_l);
    SYM(PT2.h, pT2_h);   SYM(PT2.l, pT2_l);
    SYM(PZ.h, pZ_h);     SYM(PZ.l, pZ_l);
    SYM(PH1r.h, pH1r_h); SYM(PH1r.l, pH1r_l);
    SYM(PT4.h, pT4_h);   SYM(PT4.l, pT4_l);
    SYM(PGr.h, pGr_h);   SYM(PGr.l, pGr_l);
    SYM(POm.h, pOm_h);   SYM(POm.l, pOm_l);
    SYM(PCat.h, pCat_h); SYM(PCat.l, pCat_l);

    const Planes NONE = {nullptr, nullptr};

    // ---- one-time input/weight conversions ----
    cvt(srco, PSo, (long)4096 * 1024, 1024, 1024);
    cvt(srcr, PSr, (long)16384 * 300, 300, 304);
    cvt(Ao,   PAo, (long)8 * 512 * 512, 512, 512);
    cvt(Ar,   PAr, (long)8 * 2048 * 2048, 2048, 2048);
    cvt(Wo1,  PWo1, (long)1024 * 1024, 1024, 1024);
    cvt(Wo2,  PWo2, (long)1024 * 512, 512, 512);
    cvt(Wr1,  PWr1, (long)300 * 1024, 1024, 1024);
    cvt(Wr2,  PWr2, (long)1024 * 512, 512, 512);
    cvt(Wp,   PWp, (long)512 * 512, 512, 512);
    cvt(We,   PWe, (long)1024 * 512, 512, 512);
    pack_qkv_kernel<<<(512 * 1536 + 255) / 256, 256>>>(Wq, Wk, Wv, bq, bk, bv,
                                                       PWqkv.h, PWqkv.l, bqkv);

    // ---- GCN "o" ----
    // T1 = srco@Wo1 (planes + fp32)
    mm2(PSo, 1024, 0, PWo1, 1024, 0, nullptr, nullptr, 0,
        T1, 0, PT1, 1024, 0, ROWS_O, 1024, 1024, 1, 0);
    // H1o = relu(Ao@T1 + T1) (planes)
    mm2(PAo, 512, (long)512 * 512, PT1, 1024, (long)512 * 1024,
        nullptr, T1, (long)512 * 1024, nullptr, 0, PH1o, 1024, (long)512 * 1024,
        512, 1024, 512, B_, 1);
    // T2 = H1o@Wo2 (planes + fp32)
    mm2(PH1o, 1024, 0, PWo2, 512, 0, nullptr, nullptr, 0,
        T2, 0, PT2, 512, 0, ROWS_O, 512, 1024, 1, 0);
    // Go = relu(Ao@T2 + T2) (fp32)
    mm2(PAo, 512, (long)512 * 512, PT2, 512, (long)512 * 512,
        nullptr, T2, (long)512 * 512, Go, (long)512 * 512, NONE, 0, 0,
        512, 512, 512, B_, 1);

    // ---- GCN "r" (layer1 reassociated: relu(((Ar@x)+x)@Wr1)) ----
    // Z = Ar@srcr + srcr (planes, padded ld 304)
    mm2(PAr, 2048, (long)2048 * 2048, PSr, 304, (long)2048 * 304,
        nullptr, srcr, (long)2048 * 300, nullptr, 0, PZ, 304, (long)2048 * 304,
        2048, 300, 2048, B_, 0);
    // H1r = relu(Z@Wr1) (planes)
    mm2(PZ, 304, 0, PWr1, 1024, 0, nullptr, nullptr, 0,
        nullptr, 0, PH1r, 1024, 0, TOK, 1024, 300, 1, 1);
    // T4 = H1r@Wr2 (planes + fp32)
    mm2(PH1r, 1024, 0, PWr2, 512, 0, nullptr, nullptr, 0,
        T4, 0, PT4, 512, 0, TOK, 512, 1024, 1, 0);
    // Gr = relu(Ar@T4 + T4) (planes)
    mm2(PAr, 2048, (long)2048 * 2048, PT4, 512, (long)2048 * 512,
        nullptr, T4, (long)2048 * 512, nullptr, 0, PGr, 512, (long)2048 * 512,
        2048, 512, 2048, B_, 1);

    // ---- fused QKV projection (N=1536) ----
    mm2(PGr, 512, 0, PWqkv, 1536, 0, bqkv, nullptr, 0,
        QKV, 0, NONE, 0, 0, TOK, 1536, 512, 1, 0);

    // ---- attention (writes Om planes rows 0..2047 / 2048..4095) ----
    {
        dim3 grid(SEGS, H_);
        attn_mean_kernel<<<grid, 128>>>(QKV, POm.h, POm.l, 0);
        attn_mean_kernel<<<grid, 128>>>(QKV, POm.h, POm.l, 1);
    }

    // ---- fused Wp projection of both paths (M=4096) ----
    mm2(POm, 512, 0, PWp, 512, 0, bp, nullptr, 0,
        ao, 0, NONE, 0, 0, 4096, 512, 512, 1, 0);

    // ---- concat + final ----
    build_cat_kernel<<<(int)(((long)OUT_ROWS * 1024 + 255) / 256), 256>>>(ao, Go,
                                                                          PCat.h, PCat.l);
    mm2(PCat, 1024, 0, PWe, 512, 0, be, nullptr, 0,
        out, 0, NONE, 0, 0, OUT_ROWS, 512, 1024, 1, 0);
}

// round 9
// speedup vs baseline: 3.6183x; 1.0016x over previous
#include <cuda_runtime.h>
#include <cuda_bf16.h>
#include <cstdint>

// ---------------------------------------------------------------------------
// Problem constants: B=8, NT=32, NO=8, C=512, VD=1024, RD=300, H=4
// ---------------------------------------------------------------------------
#define B_  8
#define C_  512
#define VD_ 1024
#define RD_ 300
#define H_  4
#define DH_ 128
#define NoN 512
#define NrN 2048
#define SEGS 2048
#define TOK  16384
#define ROWS_O 4096
#define OUT_ROWS 4096

// ---------------------------------------------------------------------------
// fp32 scratch
// ---------------------------------------------------------------------------
__device__ float g_T1 [ROWS_O * 1024];
__device__ float g_T2 [ROWS_O * 512];
__device__ float g_T4 [TOK * 512];
__device__ float g_Go [ROWS_O * 512];
__device__ float g_QKV[TOK * 1536];
__device__ float g_ao [4096 * 512];
__device__ float g_bqkv[1536];

// bf16 hi/lo plane scratch
__device__ __nv_bfloat16 pAo_h [8*512*512],    pAo_l [8*512*512];
__device__ __nv_bfloat16 pAr_h [8*2048*2048],  pAr_l [8*2048*2048];
__device__ __nv_bfloat16 pSo_h [4096*1024],    pSo_l [4096*1024];
__device__ __nv_bfloat16 pSr_h [16384*304],    pSr_l [16384*304];   // ld=304
__device__ __nv_bfloat16 pWo1_h[1024*1024],    pWo1_l[1024*1024];
__device__ __nv_bfloat16 pWo2_h[1024*512],     pWo2_l[1024*512];
__device__ __nv_bfloat16 pWr1_h[300*1024],     pWr1_l[300*1024];
__device__ __nv_bfloat16 pWr2_h[1024*512],     pWr2_l[1024*512];
__device__ __nv_bfloat16 pWqkv_h[512*1536],    pWqkv_l[512*1536];
__device__ __nv_bfloat16 pWp_h [512*512],      pWp_l [512*512];
__device__ __nv_bfloat16 pWe_h [1024*512],     pWe_l [1024*512];
__device__ __nv_bfloat16 pT1_h [4096*1024],    pT1_l [4096*1024];
__device__ __nv_bfloat16 pH1o_h[4096*1024],    pH1o_l[4096*1024];
__device__ __nv_bfloat16 pT2_h [4096*512],     pT2_l [4096*512];
__device__ __nv_bfloat16 pZ_h  [16384*304],    pZ_l  [16384*304];   // ld=304
__device__ __nv_bfloat16 pH1r_h[16384*1024],   pH1r_l[16384*1024];
__device__ __nv_bfloat16 pT4_h [16384*512],    pT4_l [16384*512];
__device__ __nv_bfloat16 pGr_h [16384*512],    pGr_l [16384*512];
__device__ __nv_bfloat16 pOm_h [4096*512],     pOm_l [4096*512];
__device__ __nv_bfloat16 pCat_h[4096*1024],    pCat_l[4096*1024];

// ---------------------------------------------------------------------------
// helpers
// ---------------------------------------------------------------------------
__device__ __forceinline__ uint32_t smem_u32(const void* p) {
    uint32_t a;
    asm("{ .reg .u64 t; cvta.to.shared.u64 t, %1; cvt.u32.u64 %0, t; }"
        : "=r"(a) : "l"(p));
    return a;
}
__device__ __forceinline__ void cp16(uint32_t dst, const void* src, int sz) {
    asm volatile("cp.async.cg.shared.global [%0], [%1], 16, %2;"
                 :: "r"(dst), "l"(src), "r"(sz));
}
__device__ __forceinline__ void cp_commit() {
    asm volatile("cp.async.commit_group;");
}
__device__ __forceinline__ void cp_wait(int pend) {
    if (pend >= 1) asm volatile("cp.async.wait_group 1;");
    else           asm volatile("cp.async.wait_group 0;");
}
__device__ __forceinline__ void ldsm4(uint32_t* r, uint32_t addr) {
    asm volatile("ldmatrix.sync.aligned.m8n8.x4.shared.b16 {%0,%1,%2,%3}, [%4];"
                 : "=r"(r[0]), "=r"(r[1]), "=r"(r[2]), "=r"(r[3]) : "r"(addr));
}
__device__ __forceinline__ void ldsm4t(uint32_t* r, uint32_t addr) {
    asm volatile("ldmatrix.sync.aligned.m8n8.x4.trans.shared.b16 {%0,%1,%2,%3}, [%4];"
                 : "=r"(r[0]), "=r"(r[1]), "=r"(r[2]), "=r"(r[3]) : "r"(addr));
}
__device__ __forceinline__ void mma16816(float* d, const uint32_t* a, const uint32_t* b) {
    asm volatile(
        "mma.sync.aligned.m16n8k16.row.col.f32.bf16.bf16.f32 "
        "{%0,%1,%2,%3}, {%4,%5,%6,%7}, {%8,%9}, {%0,%1,%2,%3};"
        : "+f"(d[0]), "+f"(d[1]), "+f"(d[2]), "+f"(d[3])
        : "r"(a[0]), "r"(a[1]), "r"(a[2]), "r"(a[3]), "r"(b[0]), "r"(b[1]));
}
__device__ __forceinline__ void split1(float x, __nv_bfloat16& h, __nv_bfloat16& l) {
    h = __float2bfloat16(x);
    l = __float2bfloat16(x - __bfloat162float(h));
}

// ---------------------------------------------------------------------------
// SMEM stage layout (bytes)
// ---------------------------------------------------------------------------
#define PITCH_A 80
#define PITCH_B 272
#define OFF_AL 10240
#define OFF_BH 20480
#define OFF_BL 29184
#define STAGE_B 37888
#define NSTAGE 3
#define SMEM_DYN (NSTAGE * STAGE_B)     // 113664

// ---------------------------------------------------------------------------
// HMMA bf16-split GEMM v3: pre-split bf16 planes, cp.async 3-stage pipeline,
// one __syncthreads per chunk, ldsm4t for B, term-major MMA ordering.
// ---------------------------------------------------------------------------
__global__ __launch_bounds__(256, 1)
void mm2_kernel(const __nv_bfloat16* __restrict__ Ah, const __nv_bfloat16* __restrict__ Al,
                int lda, long sAp,
                const __nv_bfloat16* __restrict__ Bh, const __nv_bfloat16* __restrict__ Bl,
                int ldb, long sBp,
                const float* __restrict__ bias,
                const float* __restrict__ Xadd, long sX,
                float* __restrict__ Cf, long sCf,
                __nv_bfloat16* __restrict__ Ch, __nv_bfloat16* __restrict__ Cl,
                int ldo, long sCo,
                int M, int N, int K, int relu)
{
    extern __shared__ char smem[];
    const uint32_t sbase = smem_u32(smem);

    const int bz = blockIdx.z;
    Ah += (long)bz * sAp;  Al += (long)bz * sAp;
    Bh += (long)bz * sBp;  Bl += (long)bz * sBp;
    if (Cf) Cf += (long)bz * sCf;
    if (Ch) { Ch += (long)bz * sCo; Cl += (long)bz * sCo; }
    const float* X = Xadd ? (Xadd + (long)bz * sX) : nullptr;

    const int tid  = threadIdx.x;
    const int wid  = tid >> 5;
    const int lane = tid & 31;
    const int row0 = blockIdx.y * 128;
    const int col0 = blockIdx.x * 128;
    const int wm = wid >> 2;
    const int wn = wid & 3;

    float acc[4][4][4];
    #pragma unroll
    for (int mt = 0; mt < 4; ++mt)
        #pragma unroll
        for (int nt = 0; nt < 4; ++nt)
            #pragma unroll
            for (int e = 0; e < 4; ++e) acc[mt][nt][e] = 0.f;

    const int nch = (K + 31) >> 5;

    auto issueStage = [&](int c, int buf) {
        const int k0 = c << 5;
        const uint32_t sb = sbase + buf * STAGE_B;
        #pragma unroll
        for (int i = 0; i < 2; ++i) {
            const int ch  = tid + i * 256;
            const int row = ch >> 2;
            const int o8  = (ch & 3) * 8;
            const int rem = K - (k0 + o8);
            const int sz  = rem >= 8 ? 16 : (rem > 0 ? rem * 2 : 0);
            const long so = (long)(row0 + row) * lda + (sz ? (k0 + o8) : 0);
            const uint32_t d = sb + row * PITCH_A + (ch & 3) * 16;
            cp16(d,          Ah + so, sz);
            cp16(d + OFF_AL, Al + so, sz);
        }
        #pragma unroll
        for (int i = 0; i < 2; ++i) {
            const int ch   = tid + i * 256;
            const int krow = ch >> 4;
            const int no8  = (ch & 15) * 8;
            const int remn = N - (col0 + no8);
            int sz = (k0 + krow < K) ? (remn >= 8 ? 16 : (remn > 0 ? remn * 2 : 0)) : 0;
            const long so = sz ? ((long)(k0 + krow) * ldb + col0 + no8) : 0;
            const uint32_t d = sb + OFF_BH + krow * PITCH_B + (ch & 15) * 16;
            cp16(d,                     Bh + so, sz);
            cp16(d + (OFF_BL - OFF_BH), Bl + so, sz);
        }
    };

    auto computeChunk = [&](int buf) {
        const uint32_t sb = sbase + buf * STAGE_B;
        #pragma unroll
        for (int kb = 0; kb < 32; kb += 16) {
            uint32_t ahf[4][4], alf[4][4], bhf[4][2], blf[4][2];
            #pragma unroll
            for (int mt = 0; mt < 4; ++mt) {
                const uint32_t arow = wm * 64 + mt * 16 + (lane & 15);
                const uint32_t aoff = sb + arow * PITCH_A + (kb + ((lane >> 4) * 8)) * 2;
                ldsm4(ahf[mt], aoff);
                ldsm4(alf[mt], aoff + OFF_AL);
            }
            // B: ldsm4t covers two nt blocks per call:
            //   matrix (lane>>3): 0:(kb,n0) 1:(kb+8,n0) 2:(kb,n0+8) 3:(kb+8,n0+8)
            #pragma unroll
            for (int pair = 0; pair < 2; ++pair) {
                const uint32_t krow = kb + ((lane >> 3) & 1) * 8 + (lane & 7);
                const uint32_t ncol = wn * 32 + pair * 16 + (lane >> 4) * 8;
                const uint32_t boff = sb + OFF_BH + krow * PITCH_B + ncol * 2;
                uint32_t r4[4];
                ldsm4t(r4, boff);
                bhf[pair * 2][0] = r4[0]; bhf[pair * 2][1] = r4[1];
                bhf[pair * 2 + 1][0] = r4[2]; bhf[pair * 2 + 1][1] = r4[3];
                ldsm4t(r4, boff + (OFF_BL - OFF_BH));
                blf[pair * 2][0] = r4[0]; blf[pair * 2][1] = r4[1];
                blf[pair * 2 + 1][0] = r4[2]; blf[pair * 2 + 1][1] = r4[3];
            }
            // term-major: 16 independent MMAs per term
            #pragma unroll
            for (int mt = 0; mt < 4; ++mt)
                #pragma unroll
                for (int nt = 0; nt < 4; ++nt)
                    mma16816(acc[mt][nt], ahf[mt], bhf[nt]);
            #pragma unroll
            for (int mt = 0; mt < 4; ++mt)
                #pragma unroll
                for (int nt = 0; nt < 4; ++nt)
                    mma16816(acc[mt][nt], alf[mt], bhf[nt]);
            #pragma unroll
            for (int mt = 0; mt < 4; ++mt)
                #pragma unroll
                for (int nt = 0; nt < 4; ++nt)
                    mma16816(acc[mt][nt], ahf[mt], blf[nt]);
        }
    };

    // prologue: stages 0,1 in flight
    issueStage(0, 0); cp_commit();
    if (nch > 1) { issueStage(1, 1); cp_commit(); }

    for (int c = 0; c < nch; ++c) {
        // ensure group c landed (allow group c+1 to stay pending)
        cp_wait((c + 2 <= nch) ? ((c + 1 < nch) ? 1 : 0) : 0);
        __syncthreads();                 // retires stage (c-1) for all warps
        if (c + 2 < nch) { issueStage(c + 2, (c + 2) % NSTAGE); cp_commit(); }
        computeChunk(c % NSTAGE);
    }

    // epilogue
    #pragma unroll
    for (int mt = 0; mt < 4; ++mt) {
        #pragma unroll
        for (int nt = 0; nt < 4; ++nt) {
            const int col = col0 + wn * 32 + nt * 8 + (lane & 3) * 2;
            if (col >= N) continue;
            #pragma unroll
            for (int half = 0; half < 2; ++half) {
                const int row = row0 + wm * 64 + mt * 16 + (lane >> 2) + half * 8;
                float2 v = make_float2(acc[mt][nt][half * 2], acc[mt][nt][half * 2 + 1]);
                if (bias) {
                    const float2 bv = *(const float2*)(bias + col);
                    v.x += bv.x; v.y += bv.y;
                }
                if (X) {
                    const float2 xv = *(const float2*)(X + (long)row * N + col);
                    v.x += xv.x; v.y += xv.y;
                }
                if (relu) { v.x = fmaxf(v.x, 0.f); v.y = fmaxf(v.y, 0.f); }
                if (Cf) *(float2*)(Cf + (long)row * N + col) = v;
                if (Ch) {
                    __nv_bfloat16 hx, lx, hy, ly;
                    split1(v.x, hx, lx); split1(v.y, hy, ly);
                    const long o = (long)row * ldo + col;
                    *(uint32_t*)(Ch + o) =
                        (uint32_t)__bfloat16_as_ushort(hx) | ((uint32_t)__bfloat16_as_ushort(hy) << 16);
                    *(uint32_t*)(Cl + o) =
                        (uint32_t)__bfloat16_as_ushort(lx) | ((uint32_t)__bfloat16_as_ushort(ly) << 16);
                }
            }
        }
    }
}

// ---------------------------------------------------------------------------
// fp32 -> bf16 hi/lo plane convert
// ---------------------------------------------------------------------------
__global__ __launch_bounds__(256)
void cvt_kernel(const float* __restrict__ in, __nv_bfloat16* __restrict__ h,
                __nv_bfloat16* __restrict__ l, long n, int cols, int ldo)
{
    const long i = ((long)blockIdx.x * 256 + threadIdx.x) * 4;
    if (i >= n) return;
    const float4 v = *(const float4*)(in + i);
    long o;
    if (cols == ldo) o = i;
    else { const long r = i / cols; o = r * ldo + (int)(i - r * cols); }
    __nv_bfloat16 hh[4], ll[4];
    split1(v.x, hh[0], ll[0]); split1(v.y, hh[1], ll[1]);
    split1(v.z, hh[2], ll[2]); split1(v.w, hh[3], ll[3]);
    *(uint2*)(h + o) = *(uint2*)hh;
    *(uint2*)(l + o) = *(uint2*)ll;
}

__global__ __launch_bounds__(256)
void pack_qkv_kernel(const float* __restrict__ Wq, const float* __restrict__ Wk,
                     const float* __restrict__ Wv, const float* __restrict__ bq,
                     const float* __restrict__ bk, const float* __restrict__ bv,
                     __nv_bfloat16* __restrict__ h, __nv_bfloat16* __restrict__ l,
                     float* __restrict__ bias)
{
    const int idx = blockIdx.x * 256 + threadIdx.x;
    if (idx < 512 * 1536) {
        const int k = idx / 1536, n = idx % 1536, sel = n >> 9;
        const float* W = (sel == 0) ? Wq : (sel == 1) ? Wk : Wv;
        const float v = W[k * 512 + (n & 511)];
        __nv_bfloat16 hh, ll; split1(v, hh, ll);
        h[idx] = hh; l[idx] = ll;
    }
    if (idx < 1536) {
        const int sel = idx >> 9;
        const float* bb = (sel == 0) ? bq : (sel == 1) ? bk : bv;
        bias[idx] = bb[idx & 511];
    }
}

// ---------------------------------------------------------------------------
// Segmented MHA, both paths in one launch (blockIdx.z = path)
// ---------------------------------------------------------------------------
__global__ __launch_bounds__(128)
void attn_mean_kernel(const float* __restrict__ QKV,
                      __nv_bfloat16* __restrict__ OmH, __nv_bfloat16* __restrict__ OmL)
{
    const int s = blockIdx.x, h = blockIdx.y, path = blockIdx.z, tid = threadIdx.x;
    __shared__ float qs[8][DH_ + 1], ks[8][DH_ + 1], vs[8][DH_ + 1];
    __shared__ float sc[8][9], wj[8];

    #pragma unroll
    for (int i = 0; i < 8; ++i) {
        int g;
        if (path == 0) g = s * 8 + i;
        else { const int t = s >> 3, j = s & 7; g = t * 64 + i * 8 + j; }
        const long off = (long)g * 1536 + h * DH_ + tid;
        qs[i][tid] = QKV[off];
        ks[i][tid] = QKV[off + 512];
        vs[i][tid] = QKV[off + 1024];
    }
    __syncthreads();

    if (tid < 64) {
        const int i = tid >> 3, j = tid & 7;
        float d = 0.f;
        #pragma unroll 16
        for (int k = 0; k < DH_; ++k) d = fmaf(qs[i][k], ks[j][k], d);
        sc[i][j] = d * 0.08838834764831845f;
    }
    __syncthreads();
    if (tid < 8) {
        const int i = tid;
        float m = -1e30f;
        #pragma unroll
        for (int j = 0; j < 8; ++j) m = fmaxf(m, sc[i][j]);
        float e[8], sum = 0.f;
        #pragma unroll
        for (int j = 0; j < 8; ++j) { e[j] = __expf(sc[i][j] - m); sum += e[j]; }
        const float inv = 1.f / sum;
        #pragma unroll
        for (int j = 0; j < 8; ++j) sc[i][j] = e[j] * inv;
    }
    __syncthreads();
    if (tid < 8) {
        const int j = tid;
        float w = 0.f;
        #pragma unroll
        for (int i = 0; i < 8; ++i) w += sc[i][j];
        wj[j] = w * 0.125f;
    }
    __syncthreads();
    float o = 0.f;
    #pragma unroll
    for (int j = 0; j < 8; ++j) o = fmaf(wj[j], vs[j][tid], o);

    const long off = (long)(path * SEGS + s) * 512 + h * DH_ + tid;
    __nv_bfloat16 hh, ll; split1(o, hh, ll);
    OmH[off] = hh; OmL[off] = ll;
}

// ---------------------------------------------------------------------------
// Build cat planes
// ---------------------------------------------------------------------------
__global__ __launch_bounds__(256)
void build_cat_kernel(const float* __restrict__ ao, const float* __restrict__ Go,
                      __nv_bfloat16* __restrict__ h, __nv_bfloat16* __restrict__ l)
{
    const long idx = (long)blockIdx.x * 256 + threadIdx.x;
    if (idx >= (long)OUT_ROWS * 1024) return;
    const int row = (int)(idx >> 10);
    const int c = (int)(idx & 1023);
    float v;
    if (c < 512) {
        const int t = row >> 4, r = row & 15;
        const int arow = (r < 8) ? (t * 8 + r) : (SEGS + t * 8 + (r - 8));
        v = ao[(long)arow * 512 + c];
    } else {
        v = Go[(long)row * 512 + (c - 512)];
    }
    __nv_bfloat16 hh, ll; split1(v, hh, ll);
    h[idx] = hh; l[idx] = ll;
}

// ---------------------------------------------------------------------------
// Host
// ---------------------------------------------------------------------------
#define SYM(p, s) cudaGetSymbolAddress((void**)&p, s)

struct Planes { __nv_bfloat16 *h, *l; };

static inline void mm2(Planes A, int lda, long sAp, Planes Bp, int ldb, long sBp,
                       const float* bias, const float* X, long sX,
                       float* Cf, long sCf, Planes Co, int ldo, long sCo,
                       int M, int N, int K, int nb, int relu)
{
    dim3 grid((N + 127) / 128, M / 128, nb);
    mm2_kernel<<<grid, 256, SMEM_DYN>>>(A.h, A.l, lda, sAp, Bp.h, Bp.l, ldb, sBp,
                                        bias, X, sX, Cf, sCf, Co.h, Co.l, ldo, sCo,
                                        M, N, K, relu);
}
static inline void cvt(const float* in, Planes p, long n, int cols, int ldo)
{
    cvt_kernel<<<(int)((n / 4 + 255) / 256), 256>>>(in, p.h, p.l, n, cols, ldo);
}

extern "C" void kernel_launch(void* const* d_in, const int* in_sizes, int n_in,
                              void* d_out, int out_size)
{
    const float* Ao   = (const float*)d_in[0];
    const float* srco = (const float*)d_in[1];
    const float* Ar   = (const float*)d_in[2];
    const float* srcr = (const float*)d_in[3];
    const float* Wo1  = (const float*)d_in[4];
    const float* Wo2  = (const float*)d_in[5];
    const float* Wr1  = (const float*)d_in[6];
    const float* Wr2  = (const float*)d_in[7];
    const float* Wq   = (const float*)d_in[8];
    const float* bq   = (const float*)d_in[9];
    const float* Wk   = (const float*)d_in[10];
    const float* bk   = (const float*)d_in[11];
    const float* Wv   = (const float*)d_in[12];
    const float* bv   = (const float*)d_in[13];
    const float* Wp   = (const float*)d_in[14];
    const float* bp   = (const float*)d_in[15];
    const float* We   = (const float*)d_in[16];
    const float* be   = (const float*)d_in[17];
    float* out = (float*)d_out;

    cudaFuncSetAttribute(mm2_kernel, cudaFuncAttributeMaxDynamicSharedMemorySize, SMEM_DYN);

    float *T1, *T2, *T4, *Go, *QKV, *ao, *bqkv;
    SYM(T1, g_T1); SYM(T2, g_T2); SYM(T4, g_T4); SYM(Go, g_Go);
    SYM(QKV, g_QKV); SYM(ao, g_ao); SYM(bqkv, g_bqkv);

    Planes PAo, PAr, PSo, PSr, PWo1, PWo2, PWr1, PWr2, PWqkv, PWp, PWe;
    Planes PT1, PH1o, PT2, PZ, PH1r, PT4, PGr, POm, PCat;
    SYM(PAo.h, pAo_h);   SYM(PAo.l, pAo_l);
    SYM(PAr.h, pAr_h);   SYM(PAr.l, pAr_l);
    SYM(PSo.h, pSo_h);   SYM(PSo.l, pSo_l);
    SYM(PSr.h, pSr_h);   SYM(PSr.l, pSr_l);
    SYM(PWo1.h, pWo1_h); SYM(PWo1.l, pWo1_l);
    SYM(PWo2.h, pWo2_h); SYM(PWo2.l, pWo2_l);
    SYM(PWr1.h, pWr1_h); SYM(PWr1.l, pWr1_l);
    SYM(PWr2.h, pWr2_h); SYM(PWr2.l, pWr2_l);
    SYM(PWqkv.h, pWqkv_h); SYM(PWqkv.l, pWqkv_l);
    SYM(PWp.h, pWp_h);   SYM(PWp.l, pWp_l);
    SYM(PWe.h, pWe_h);   SYM(PWe.l, pWe_l);
    SYM(PT1.h, pT1_h);   SYM(PT1.l, pT1_l);
    SYM(PH1o.h, pH1o_h); SYM(PH1o.l, pH1o_l);
    SYM(PT2.h, pT2_h);   SYM(PT2.l, pT2_l);
    SYM(PZ.h, pZ_h);     SYM(PZ.l, pZ_l);
    SYM(PH1r.h, pH1r_h); SYM(PH1r.l, pH1r_l);
    SYM(PT4.h, pT4_h);   SYM(PT4.l, pT4_l);
    SYM(PGr.h, pGr_h);   SYM(PGr.l, pGr_l);
    SYM(POm.h, pOm_h);   SYM(POm.l, pOm_l);
    SYM(PCat.h, pCat_h); SYM(PCat.l, pCat_l);

    const Planes NONE = {nullptr, nullptr};

    // ---- one-time input/weight conversions ----
    cvt(srco, PSo, (long)4096 * 1024, 1024, 1024);
    cvt(srcr, PSr, (long)16384 * 300, 300, 304);
    cvt(Ao,   PAo, (long)8 * 512 * 512, 512, 512);
    cvt(Ar,   PAr, (long)8 * 2048 * 2048, 2048, 2048);
    cvt(Wo1,  PWo1, (long)1024 * 1024, 1024, 1024);
    cvt(Wo2,  PWo2, (long)1024 * 512, 512, 512);
    cvt(Wr1,  PWr1, (long)300 * 1024, 1024, 1024);
    cvt(Wr2,  PWr2, (long)1024 * 512, 512, 512);
    cvt(Wp,   PWp, (long)512 * 512, 512, 512);
    cvt(We,   PWe, (long)1024 * 512, 512, 512);
    pack_qkv_kernel<<<(512 * 1536 + 255) / 256, 256>>>(Wq, Wk, Wv, bq, bk, bv,
                                                       PWqkv.h, PWqkv.l, bqkv);

    // ---- GCN "o" ----
    mm2(PSo, 1024, 0, PWo1, 1024, 0, nullptr, nullptr, 0,
        T1, 0, PT1, 1024, 0, ROWS_O, 1024, 1024, 1, 0);
    mm2(PAo, 512, (long)512 * 512, PT1, 1024, (long)512 * 1024,
        nullptr, T1, (long)512 * 1024, nullptr, 0, PH1o, 1024, (long)512 * 1024,
        512, 1024, 512, B_, 1);
    mm2(PH1o, 1024, 0, PWo2, 512, 0, nullptr, nullptr, 0,
        T2, 0, PT2, 512, 0, ROWS_O, 512, 1024, 1, 0);
    mm2(PAo, 512, (long)512 * 512, PT2, 512, (long)512 * 512,
        nullptr, T2, (long)512 * 512, Go, (long)512 * 512, NONE, 0, 0,
        512, 512, 512, B_, 1);

    // ---- GCN "r" (layer1 reassociated) ----
    mm2(PAr, 2048, (long)2048 * 2048, PSr, 304, (long)2048 * 304,
        nullptr, srcr, (long)2048 * 300, nullptr, 0, PZ, 304, (long)2048 * 304,
        2048, 300, 2048, B_, 0);
    mm2(PZ, 304, 0, PWr1, 1024, 0, nullptr, nullptr, 0,
        nullptr, 0, PH1r, 1024, 0, TOK, 1024, 300, 1, 1);
    mm2(PH1r, 1024, 0, PWr2, 512, 0, nullptr, nullptr, 0,
        T4, 0, PT4, 512, 0, TOK, 512, 1024, 1, 0);
    mm2(PAr, 2048, (long)2048 * 2048, PT4, 512, (long)2048 * 512,
        nullptr, T4, (long)2048 * 512, nullptr, 0, PGr, 512, (long)2048 * 512,
        2048, 512, 2048, B_, 1);

    // ---- fused QKV ----
    mm2(PGr, 512, 0, PWqkv, 1536, 0, bqkv, nullptr, 0,
        QKV, 0, NONE, 0, 0, TOK, 1536, 512, 1, 0);

    // ---- attention (both paths, one launch) ----
    {
        dim3 grid(SEGS, H_, 2);
        attn_mean_kernel<<<grid, 128>>>(QKV, POm.h, POm.l);
    }

    // ---- fused Wp projection ----
    mm2(POm, 512, 0, PWp, 512, 0, bp, nullptr, 0,
        ao, 0, NONE, 0, 0, 4096, 512, 512, 1, 0);

    // ---- concat + final ----
    build_cat_kernel<<<(int)(((long)OUT_ROWS * 1024 + 255) / 256), 256>>>(ao, Go,
                                                                          PCat.h, PCat.l);
    mm2(PCat, 1024, 0, PWe, 512, 0, be, nullptr, 0,
        out, 0, NONE, 0, 0, OUT_ROWS, 512, 1024, 1, 0);
}

// round 10
// speedup vs baseline: 4.2530x; 1.1754x over previous
#include <cuda_runtime.h>
#include <cuda_bf16.h>
#include <cstdint>

// ---------------------------------------------------------------------------
// Problem constants: B=8, NT=32, NO=8, C=512, VD=1024, RD=300, H=4
// ---------------------------------------------------------------------------
#define B_  8
#define C_  512
#define VD_ 1024
#define RD_ 300
#define H_  4
#define DH_ 128
#define NoN 512
#define NrN 2048
#define SEGS 2048
#define TOK  16384
#define ROWS_O 4096
#define OUT_ROWS 4096

// ---------------------------------------------------------------------------
// fp32 scratch
// ---------------------------------------------------------------------------
__device__ float g_T1 [ROWS_O * 1024];
__device__ float g_T2 [ROWS_O * 512];
__device__ float g_T4 [TOK * 512];
__device__ float g_Go [ROWS_O * 512];
__device__ float g_QKV[TOK * 1536];
__device__ float g_ao [4096 * 512];
__device__ float g_bqkv[1536];

// bf16 hi/lo plane scratch
__device__ __nv_bfloat16 pAo_h [8*512*512],    pAo_l [8*512*512];
__device__ __nv_bfloat16 pAr_h [8*2048*2048],  pAr_l [8*2048*2048];
__device__ __nv_bfloat16 pSo_h [4096*1024],    pSo_l [4096*1024];
__device__ __nv_bfloat16 pSr_h [16384*304],    pSr_l [16384*304];   // ld=304
__device__ __nv_bfloat16 pWo1_h[1024*1024],    pWo1_l[1024*1024];
__device__ __nv_bfloat16 pWo2_h[1024*512],     pWo2_l[1024*512];
__device__ __nv_bfloat16 pWr1_h[300*1024],     pWr1_l[300*1024];
__device__ __nv_bfloat16 pWr2_h[1024*512],     pWr2_l[1024*512];
__device__ __nv_bfloat16 pWqkv_h[512*1536],    pWqkv_l[512*1536];
__device__ __nv_bfloat16 pWp_h [512*512],      pWp_l [512*512];
__device__ __nv_bfloat16 pWe_h [1024*512],     pWe_l [1024*512];
__device__ __nv_bfloat16 pT1_h [4096*1024],    pT1_l [4096*1024];
__device__ __nv_bfloat16 pH1o_h[4096*1024],    pH1o_l[4096*1024];
__device__ __nv_bfloat16 pT2_h [4096*512],     pT2_l [4096*512];
__device__ __nv_bfloat16 pZ_h  [16384*304],    pZ_l  [16384*304];   // ld=304
__device__ __nv_bfloat16 pH1r_h[16384*1024],   pH1r_l[16384*1024];
__device__ __nv_bfloat16 pT4_h [16384*512],    pT4_l [16384*512];
__device__ __nv_bfloat16 pGr_h [16384*512],    pGr_l [16384*512];
__device__ __nv_bfloat16 pOm_h [4096*512],     pOm_l [4096*512];
__device__ __nv_bfloat16 pCat_h[4096*1024],    pCat_l[4096*1024];

// ---------------------------------------------------------------------------
// helpers
// ---------------------------------------------------------------------------
__device__ __forceinline__ uint32_t smem_u32(const void* p) {
    uint32_t a;
    asm("{ .reg .u64 t; cvta.to.shared.u64 t, %1; cvt.u32.u64 %0, t; }"
        : "=r"(a) : "l"(p));
    return a;
}
__device__ __forceinline__ void cp16(uint32_t dst, const void* src, int sz) {
    asm volatile("cp.async.cg.shared.global [%0], [%1], 16, %2;"
                 :: "r"(dst), "l"(src), "r"(sz));
}
__device__ __forceinline__ void cp_commit() {
    asm volatile("cp.async.commit_group;");
}
__device__ __forceinline__ void cp_wait(int pend) {
    if (pend >= 1) asm volatile("cp.async.wait_group 1;");
    else           asm volatile("cp.async.wait_group 0;");
}
__device__ __forceinline__ void ldsm4(uint32_t* r, uint32_t addr) {
    asm volatile("ldmatrix.sync.aligned.m8n8.x4.shared.b16 {%0,%1,%2,%3}, [%4];"
                 : "=r"(r[0]), "=r"(r[1]), "=r"(r[2]), "=r"(r[3]) : "r"(addr));
}
__device__ __forceinline__ void ldsm4t(uint32_t* r, uint32_t addr) {
    asm volatile("ldmatrix.sync.aligned.m8n8.x4.trans.shared.b16 {%0,%1,%2,%3}, [%4];"
                 : "=r"(r[0]), "=r"(r[1]), "=r"(r[2]), "=r"(r[3]) : "r"(addr));
}
__device__ __forceinline__ void mma16816(float* d, const uint32_t* a, const uint32_t* b) {
    asm volatile(
        "mma.sync.aligned.m16n8k16.row.col.f32.bf16.bf16.f32 "
        "{%0,%1,%2,%3}, {%4,%5,%6,%7}, {%8,%9}, {%0,%1,%2,%3};"
        : "+f"(d[0]), "+f"(d[1]), "+f"(d[2]), "+f"(d[3])
        : "r"(a[0]), "r"(a[1]), "r"(a[2]), "r"(a[3]), "r"(b[0]), "r"(b[1]));
}
__device__ __forceinline__ void split1(float x, __nv_bfloat16& h, __nv_bfloat16& l) {
    h = __float2bfloat16(x);
    l = __float2bfloat16(x - __bfloat162float(h));
}

// ---------------------------------------------------------------------------
// SMEM stage layout (bytes)
// ---------------------------------------------------------------------------
#define PITCH_A 80
#define PITCH_B 272
#define OFF_AL 10240
#define OFF_BH 20480
#define OFF_BL 29184
#define STAGE_B 37888
#define NSTAGE 3
#define SMEM_DYN (NSTAGE * STAGE_B)     // 113664 -> 2 CTAs = 227328 <= 228KB/SM

// ---------------------------------------------------------------------------
// HMMA bf16-split GEMM v4: 128 threads/CTA (2x2 warps, 64x64 warp tile),
// 128x128 CTA tile, 3-stage cp.async pipeline, 2 CTAs/SM co-residency.
// ---------------------------------------------------------------------------
__global__ __launch_bounds__(128, 2)
void mm2_kernel(const __nv_bfloat16* __restrict__ Ah, const __nv_bfloat16* __restrict__ Al,
                int lda, long sAp,
                const __nv_bfloat16* __restrict__ Bh, const __nv_bfloat16* __restrict__ Bl,
                int ldb, long sBp,
                const float* __restrict__ bias,
                const float* __restrict__ Xadd, long sX,
                float* __restrict__ Cf, long sCf,
                __nv_bfloat16* __restrict__ Ch, __nv_bfloat16* __restrict__ Cl,
                int ldo, long sCo,
                int M, int N, int K, int relu)
{
    extern __shared__ char smem[];
    const uint32_t sbase = smem_u32(smem);

    const int bz = blockIdx.z;
    Ah += (long)bz * sAp;  Al += (long)bz * sAp;
    Bh += (long)bz * sBp;  Bl += (long)bz * sBp;
    if (Cf) Cf += (long)bz * sCf;
    if (Ch) { Ch += (long)bz * sCo; Cl += (long)bz * sCo; }
    const float* X = Xadd ? (Xadd + (long)bz * sX) : nullptr;

    const int tid  = threadIdx.x;        // 0..127
    const int wid  = tid >> 5;           // 0..3
    const int lane = tid & 31;
    const int row0 = blockIdx.y * 128;
    const int col0 = blockIdx.x * 128;
    const int wm = wid >> 1;             // 0..1 -> rows wm*64
    const int wn = wid & 1;              // 0..1 -> cols wn*64

    float acc[4][8][4];
    #pragma unroll
    for (int mt = 0; mt < 4; ++mt)
        #pragma unroll
        for (int nt = 0; nt < 8; ++nt)
            #pragma unroll
            for (int e = 0; e < 4; ++e) acc[mt][nt][e] = 0.f;

    const int nch = (K + 31) >> 5;

    auto issueStage = [&](int c, int buf) {
        const int k0 = c << 5;
        const uint32_t sb = sbase + buf * STAGE_B;
        // A planes: 512 x 16B chunks each; 4 per thread per plane
        #pragma unroll
        for (int i = 0; i < 4; ++i) {
            const int ch  = tid + i * 128;
            const int row = ch >> 2;
            const int o8  = (ch & 3) * 8;
            const int rem = K - (k0 + o8);
            const int sz  = rem >= 8 ? 16 : (rem > 0 ? rem * 2 : 0);
            const long so = (long)(row0 + row) * lda + (sz ? (k0 + o8) : 0);
            const uint32_t d = sb + row * PITCH_A + (ch & 3) * 16;
            cp16(d,          Ah + so, sz);
            cp16(d + OFF_AL, Al + so, sz);
        }
        // B planes: 512 x 16B chunks each; 4 per thread per plane
        #pragma unroll
        for (int i = 0; i < 4; ++i) {
            const int ch   = tid + i * 128;
            const int krow = ch >> 4;
            const int no8  = (ch & 15) * 8;
            const int remn = N - (col0 + no8);
            int sz = (k0 + krow < K) ? (remn >= 8 ? 16 : (remn > 0 ? remn * 2 : 0)) : 0;
            const long so = sz ? ((long)(k0 + krow) * ldb + col0 + no8) : 0;
            const uint32_t d = sb + OFF_BH + krow * PITCH_B + (ch & 15) * 16;
            cp16(d,                     Bh + so, sz);
            cp16(d + (OFF_BL - OFF_BH), Bl + so, sz);
        }
    };

    auto computeChunk = [&](int buf) {
        const uint32_t sb = sbase + buf * STAGE_B;
        #pragma unroll
        for (int kb = 0; kb < 32; kb += 16) {
            uint32_t ahf[4][4], alf[4][4], bhf[8][2], blf[8][2];
            #pragma unroll
            for (int mt = 0; mt < 4; ++mt) {
                const uint32_t arow = wm * 64 + mt * 16 + (lane & 15);
                const uint32_t aoff = sb + arow * PITCH_A + (kb + ((lane >> 4) * 8)) * 2;
                ldsm4(ahf[mt], aoff);
                ldsm4(alf[mt], aoff + OFF_AL);
            }
            // B: each ldsm4t covers two 8-col blocks
            #pragma unroll
            for (int pair = 0; pair < 4; ++pair) {
                const uint32_t krow = kb + ((lane >> 3) & 1) * 8 + (lane & 7);
                const uint32_t ncol = wn * 64 + pair * 16 + (lane >> 4) * 8;
                const uint32_t boff = sb + OFF_BH + krow * PITCH_B + ncol * 2;
                uint32_t r4[4];
                ldsm4t(r4, boff);
                bhf[pair * 2][0] = r4[0]; bhf[pair * 2][1] = r4[1];
                bhf[pair * 2 + 1][0] = r4[2]; bhf[pair * 2 + 1][1] = r4[3];
                ldsm4t(r4, boff + (OFF_BL - OFF_BH));
                blf[pair * 2][0] = r4[0]; blf[pair * 2][1] = r4[1];
                blf[pair * 2 + 1][0] = r4[2]; blf[pair * 2 + 1][1] = r4[3];
            }
            // term-major: 32 independent MMAs per term
            #pragma unroll
            for (int mt = 0; mt < 4; ++mt)
                #pragma unroll
                for (int nt = 0; nt < 8; ++nt)
                    mma16816(acc[mt][nt], ahf[mt], bhf[nt]);
            #pragma unroll
            for (int mt = 0; mt < 4; ++mt)
                #pragma unroll
                for (int nt = 0; nt < 8; ++nt)
                    mma16816(acc[mt][nt], alf[mt], bhf[nt]);
            #pragma unroll
            for (int mt = 0; mt < 4; ++mt)
                #pragma unroll
                for (int nt = 0; nt < 8; ++nt)
                    mma16816(acc[mt][nt], ahf[mt], blf[nt]);
        }
    };

    // prologue: stages 0,1 in flight
    issueStage(0, 0); cp_commit();
    if (nch > 1) { issueStage(1, 1); cp_commit(); }

    for (int c = 0; c < nch; ++c) {
        cp_wait((c + 2 <= nch) ? ((c + 1 < nch) ? 1 : 0) : 0);
        __syncthreads();
        if (c + 2 < nch) { issueStage(c + 2, (c + 2) % NSTAGE); cp_commit(); }
        computeChunk(c % NSTAGE);
    }

    // epilogue
    #pragma unroll
    for (int mt = 0; mt < 4; ++mt) {
        #pragma unroll
        for (int nt = 0; nt < 8; ++nt) {
            const int col = col0 + wn * 64 + nt * 8 + (lane & 3) * 2;
            if (col >= N) continue;
            #pragma unroll
            for (int half = 0; half < 2; ++half) {
                const int row = row0 + wm * 64 + mt * 16 + (lane >> 2) + half * 8;
                float2 v = make_float2(acc[mt][nt][half * 2], acc[mt][nt][half * 2 + 1]);
                if (bias) {
                    const float2 bv = *(const float2*)(bias + col);
                    v.x += bv.x; v.y += bv.y;
                }
                if (X) {
                    const float2 xv = *(const float2*)(X + (long)row * N + col);
                    v.x += xv.x; v.y += xv.y;
                }
                if (relu) { v.x = fmaxf(v.x, 0.f); v.y = fmaxf(v.y, 0.f); }
                if (Cf) *(float2*)(Cf + (long)row * N + col) = v;
                if (Ch) {
                    __nv_bfloat16 hx, lx, hy, ly;
                    split1(v.x, hx, lx); split1(v.y, hy, ly);
                    const long o = (long)row * ldo + col;
                    *(uint32_t*)(Ch + o) =
                        (uint32_t)__bfloat16_as_ushort(hx) | ((uint32_t)__bfloat16_as_ushort(hy) << 16);
                    *(uint32_t*)(Cl + o) =
                        (uint32_t)__bfloat16_as_ushort(lx) | ((uint32_t)__bfloat16_as_ushort(ly) << 16);
                }
            }
        }
    }
}

// ---------------------------------------------------------------------------
// fp32 -> bf16 hi/lo plane convert
// ---------------------------------------------------------------------------
__global__ __launch_bounds__(256)
void cvt_kernel(const float* __restrict__ in, __nv_bfloat16* __restrict__ h,
                __nv_bfloat16* __restrict__ l, long n, int cols, int ldo)
{
    const long i = ((long)blockIdx.x * 256 + threadIdx.x) * 4;
    if (i >= n) return;
    const float4 v = *(const float4*)(in + i);
    long o;
    if (cols == ldo) o = i;
    else { const long r = i / cols; o = r * ldo + (int)(i - r * cols); }
    __nv_bfloat16 hh[4], ll[4];
    split1(v.x, hh[0], ll[0]); split1(v.y, hh[1], ll[1]);
    split1(v.z, hh[2], ll[2]); split1(v.w, hh[3], ll[3]);
    *(uint2*)(h + o) = *(uint2*)hh;
    *(uint2*)(l + o) = *(uint2*)ll;
}

__global__ __launch_bounds__(256)
void pack_qkv_kernel(const float* __restrict__ Wq, const float* __restrict__ Wk,
                     const float* __restrict__ Wv, const float* __restrict__ bq,
                     const float* __restrict__ bk, const float* __restrict__ bv,
                     __nv_bfloat16* __restrict__ h, __nv_bfloat16* __restrict__ l,
                     float* __restrict__ bias)
{
    const int idx = blockIdx.x * 256 + threadIdx.x;
    if (idx < 512 * 1536) {
        const int k = idx / 1536, n = idx % 1536, sel = n >> 9;
        const float* W = (sel == 0) ? Wq : (sel == 1) ? Wk : Wv;
        const float v = W[k * 512 + (n & 511)];
        __nv_bfloat16 hh, ll; split1(v, hh, ll);
        h[idx] = hh; l[idx] = ll;
    }
    if (idx < 1536) {
        const int sel = idx >> 9;
        const float* bb = (sel == 0) ? bq : (sel == 1) ? bk : bv;
        bias[idx] = bb[idx & 511];
    }
}

// ---------------------------------------------------------------------------
// Segmented MHA, both paths in one launch (blockIdx.z = path)
// ---------------------------------------------------------------------------
__global__ __launch_bounds__(128)
void attn_mean_kernel(const float* __restrict__ QKV,
                      __nv_bfloat16* __restrict__ OmH, __nv_bfloat16* __restrict__ OmL)
{
    const int s = blockIdx.x, h = blockIdx.y, path = blockIdx.z, tid = threadIdx.x;
    __shared__ float qs[8][DH_ + 1], ks[8][DH_ + 1], vs[8][DH_ + 1];
    __shared__ float sc[8][9], wj[8];

    #pragma unroll
    for (int i = 0; i < 8; ++i) {
        int g;
        if (path == 0) g = s * 8 + i;
        else { const int t = s >> 3, j = s & 7; g = t * 64 + i * 8 + j; }
        const long off = (long)g * 1536 + h * DH_ + tid;
        qs[i][tid] = QKV[off];
        ks[i][tid] = QKV[off + 512];
        vs[i][tid] = QKV[off + 1024];
    }
    __syncthreads();

    if (tid < 64) {
        const int i = tid >> 3, j = tid & 7;
        float d = 0.f;
        #pragma unroll 16
        for (int k = 0; k < DH_; ++k) d = fmaf(qs[i][k], ks[j][k], d);
        sc[i][j] = d * 0.08838834764831845f;
    }
    __syncthreads();
    if (tid < 8) {
        const int i = tid;
        float m = -1e30f;
        #pragma unroll
        for (int j = 0; j < 8; ++j) m = fmaxf(m, sc[i][j]);
        float e[8], sum = 0.f;
        #pragma unroll
        for (int j = 0; j < 8; ++j) { e[j] = __expf(sc[i][j] - m); sum += e[j]; }
        const float inv = 1.f / sum;
        #pragma unroll
        for (int j = 0; j < 8; ++j) sc[i][j] = e[j] * inv;
    }
    __syncthreads();
    if (tid < 8) {
        const int j = tid;
        float w = 0.f;
        #pragma unroll
        for (int i = 0; i < 8; ++i) w += sc[i][j];
        wj[j] = w * 0.125f;
    }
    __syncthreads();
    float o = 0.f;
    #pragma unroll
    for (int j = 0; j < 8; ++j) o = fmaf(wj[j], vs[j][tid], o);

    const long off = (long)(path * SEGS + s) * 512 + h * DH_ + tid;
    __nv_bfloat16 hh, ll; split1(o, hh, ll);
    OmH[off] = hh; OmL[off] = ll;
}

// ---------------------------------------------------------------------------
// Build cat planes
// ---------------------------------------------------------------------------
__global__ __launch_bounds__(256)
void build_cat_kernel(const float* __restrict__ ao, const float* __restrict__ Go,
                      __nv_bfloat16* __restrict__ h, __nv_bfloat16* __restrict__ l)
{
    const long idx = (long)blockIdx.x * 256 + threadIdx.x;
    if (idx >= (long)OUT_ROWS * 1024) return;
    const int row = (int)(idx >> 10);
    const int c = (int)(idx & 1023);
    float v;
    if (c < 512) {
        const int t = row >> 4, r = row & 15;
        const int arow = (r < 8) ? (t * 8 + r) : (SEGS + t * 8 + (r - 8));
        v = ao[(long)arow * 512 + c];
    } else {
        v = Go[(long)row * 512 + (c - 512)];
    }
    __nv_bfloat16 hh, ll; split1(v, hh, ll);
    h[idx] = hh; l[idx] = ll;
}

// ---------------------------------------------------------------------------
// Host
// ---------------------------------------------------------------------------
#define SYM(p, s) cudaGetSymbolAddress((void**)&p, s)

struct Planes { __nv_bfloat16 *h, *l; };

static inline void mm2(Planes A, int lda, long sAp, Planes Bp, int ldb, long sBp,
                       const float* bias, const float* X, long sX,
                       float* Cf, long sCf, Planes Co, int ldo, long sCo,
                       int M, int N, int K, int nb, int relu)
{
    dim3 grid((N + 127) / 128, M / 128, nb);
    mm2_kernel<<<grid, 128, SMEM_DYN>>>(A.h, A.l, lda, sAp, Bp.h, Bp.l, ldb, sBp,
                                        bias, X, sX, Cf, sCf, Co.h, Co.l, ldo, sCo,
                                        M, N, K, relu);
}
static inline void cvt(const float* in, Planes p, long n, int cols, int ldo)
{
    cvt_kernel<<<(int)((n / 4 + 255) / 256), 256>>>(in, p.h, p.l, n, cols, ldo);
}

extern "C" void kernel_launch(void* const* d_in, const int* in_sizes, int n_in,
                              void* d_out, int out_size)
{
    const float* Ao   = (const float*)d_in[0];
    const float* srco = (const float*)d_in[1];
    const float* Ar   = (const float*)d_in[2];
    const float* srcr = (const float*)d_in[3];
    const float* Wo1  = (const float*)d_in[4];
    const float* Wo2  = (const float*)d_in[5];
    const float* Wr1  = (const float*)d_in[6];
    const float* Wr2  = (const float*)d_in[7];
    const float* Wq   = (const float*)d_in[8];
    const float* bq   = (const float*)d_in[9];
    const float* Wk   = (const float*)d_in[10];
    const float* bk   = (const float*)d_in[11];
    const float* Wv   = (const float*)d_in[12];
    const float* bv   = (const float*)d_in[13];
    const float* Wp   = (const float*)d_in[14];
    const float* bp   = (const float*)d_in[15];
    const float* We   = (const float*)d_in[16];
    const float* be   = (const float*)d_in[17];
    float* out = (float*)d_out;

    cudaFuncSetAttribute(mm2_kernel, cudaFuncAttributeMaxDynamicSharedMemorySize, SMEM_DYN);

    float *T1, *T2, *T4, *Go, *QKV, *ao, *bqkv;
    SYM(T1, g_T1); SYM(T2, g_T2); SYM(T4, g_T4); SYM(Go, g_Go);
    SYM(QKV, g_QKV); SYM(ao, g_ao); SYM(bqkv, g_bqkv);

    Planes PAo, PAr, PSo, PSr, PWo1, PWo2, PWr1, PWr2, PWqkv, PWp, PWe;
    Planes PT1, PH1o, PT2, PZ, PH1r, PT4, PGr, POm, PCat;
    SYM(PAo.h, pAo_h);   SYM(PAo.l, pAo_l);
    SYM(PAr.h, pAr_h);   SYM(PAr.l, pAr_l);
    SYM(PSo.h, pSo_h);   SYM(PSo.l, pSo_l);
    SYM(PSr.h, pSr_h);   SYM(PSr.l, pSr_l);
    SYM(PWo1.h, pWo1_h); SYM(PWo1.l, pWo1_l);
    SYM(PWo2.h, pWo2_h); SYM(PWo2.l, pWo2_l);
    SYM(PWr1.h, pWr1_h); SYM(PWr1.l, pWr1_l);
    SYM(PWr2.h, pWr2_h); SYM(PWr2.l, pWr2_l);
    SYM(PWqkv.h, pWqkv_h); SYM(PWqkv.l, pWqkv_l);
    SYM(PWp.h, pWp_h);   SYM(PWp.l, pWp_l);
    SYM(PWe.h, pWe_h);   SYM(PWe.l, pWe_l);
    SYM(PT1.h, pT1_h);   SYM(PT1.l, pT1_l);
    SYM(PH1o.h, pH1o_h); SYM(PH1o.l, pH1o_l);
    SYM(PT2.h, pT2_h);   SYM(PT2.l, pT2_l);
    SYM(PZ.h, pZ_h);     SYM(PZ.l, pZ_l);
    SYM(PH1r.h, pH1r_h); SYM(PH1r.l, pH1r_l);
    SYM(PT4.h, pT4_h);   SYM(PT4.l, pT4_l);
    SYM(PGr.h, pGr_h);   SYM(PGr.l, pGr_l);
    SYM(POm.h, pOm_h);   SYM(POm.l, pOm_l);
    SYM(PCat.h, pCat_h); SYM(PCat.l, pCat_l);

    const Planes NONE = {nullptr, nullptr};

    // ---- one-time input/weight conversions ----
    cvt(srco, PSo, (long)4096 * 1024, 1024, 1024);
    cvt(srcr, PSr, (long)16384 * 300, 300, 304);
    cvt(Ao,   PAo, (long)8 * 512 * 512, 512, 512);
    cvt(Ar,   PAr, (long)8 * 2048 * 2048, 2048, 2048);
    cvt(Wo1,  PWo1, (long)1024 * 1024, 1024, 1024);
    cvt(Wo2,  PWo2, (long)1024 * 512, 512, 512);
    cvt(Wr1,  PWr1, (long)300 * 1024, 1024, 1024);
    cvt(Wr2,  PWr2, (long)1024 * 512, 512, 512);
    cvt(Wp,   PWp, (long)512 * 512, 512, 512);
    cvt(We,   PWe, (long)1024 * 512, 512, 512);
    pack_qkv_kernel<<<(512 * 1536 + 255) / 256, 256>>>(Wq, Wk, Wv, bq, bk, bv,
                                                       PWqkv.h, PWqkv.l, bqkv);

    // ---- GCN "o" ----
    mm2(PSo, 1024, 0, PWo1, 1024, 0, nullptr, nullptr, 0,
        T1, 0, PT1, 1024, 0, ROWS_O, 1024, 1024, 1, 0);
    mm2(PAo, 512, (long)512 * 512, PT1, 1024, (long)512 * 1024,
        nullptr, T1, (long)512 * 1024, nullptr, 0, PH1o, 1024, (long)512 * 1024,
        512, 1024, 512, B_, 1);
    mm2(PH1o, 1024, 0, PWo2, 512, 0, nullptr, nullptr, 0,
        T2, 0, PT2, 512, 0, ROWS_O, 512, 1024, 1, 0);
    mm2(PAo, 512, (long)512 * 512, PT2, 512, (long)512 * 512,
        nullptr, T2, (long)512 * 512, Go, (long)512 * 512, NONE, 0, 0,
        512, 512, 512, B_, 1);

    // ---- GCN "r" (layer1 reassociated) ----
    mm2(PAr, 2048, (long)2048 * 2048, PSr, 304, (long)2048 * 304,
        nullptr, srcr, (long)2048 * 300, nullptr, 0, PZ, 304, (long)2048 * 304,
        2048, 300, 2048, B_, 0);
    mm2(PZ, 304, 0, PWr1, 1024, 0, nullptr, nullptr, 0,
        nullptr, 0, PH1r, 1024, 0, TOK, 1024, 300, 1, 1);
    mm2(PH1r, 1024, 0, PWr2, 512, 0, nullptr, nullptr, 0,
        T4, 0, PT4, 512, 0, TOK, 512, 1024, 1, 0);
    mm2(PAr, 2048, (long)2048 * 2048, PT4, 512, (long)2048 * 512,
        nullptr, T4, (long)2048 * 512, nullptr, 0, PGr, 512, (long)2048 * 512,
        2048, 512, 2048, B_, 1);

    // ---- fused QKV ----
    mm2(PGr, 512, 0, PWqkv, 1536, 0, bqkv, nullptr, 0,
        QKV, 0, NONE, 0, 0, TOK, 1536, 512, 1, 0);

    // ---- attention (both paths, one launch) ----
    {
        dim3 grid(SEGS, H_, 2);
        attn_mean_kernel<<<grid, 128>>>(QKV, POm.h, POm.l);
    }

    // ---- fused Wp projection ----
    mm2(POm, 512, 0, PWp, 512, 0, bp, nullptr, 0,
        ao, 0, NONE, 0, 0, 4096, 512, 512, 1, 0);

    // ---- concat + final ----
    build_cat_kernel<<<(int)(((long)OUT_ROWS * 1024 + 255) / 256), 256>>>(ao, Go,
                                                                          PCat.h, PCat.l);
    mm2(PCat, 1024, 0, PWe, 512, 0, be, nullptr, 0,
        out, 0, NONE, 0, 0, OUT_ROWS, 512, 1024, 1, 0);
}

// round 12
// speedup vs baseline: 4.3003x; 1.0111x over previous
#include <cuda_runtime.h>
#include <cuda_bf16.h>
#include <cstdint>

// ---------------------------------------------------------------------------
// Problem constants: B=8, NT=32, NO=8, C=512, VD=1024, RD=300, H=4
// ---------------------------------------------------------------------------
#define B_  8
#define C_  512
#define H_  4
#define DH_ 128
#define SEGS 2048
#define TOK  16384
#define ROWS_O 4096
#define OUT_ROWS 4096

// ---------------------------------------------------------------------------
// fp32 scratch
// ---------------------------------------------------------------------------
__device__ float g_T1 [ROWS_O * 1024];
__device__ float g_T2 [ROWS_O * 512];
__device__ float g_T4 [TOK * 512];
__device__ float g_QKV[TOK * 1536];
__device__ float g_bqkv[1536];

// bf16 hi/lo plane scratch
__device__ __nv_bfloat16 pAo_h [8*512*512],    pAo_l [8*512*512];
__device__ __nv_bfloat16 pAr_h [8*2048*2048],  pAr_l [8*2048*2048];
__device__ __nv_bfloat16 pSo_h [4096*1024],    pSo_l [4096*1024];
__device__ __nv_bfloat16 pSr_h [16384*304],    pSr_l [16384*304];   // ld=304
__device__ __nv_bfloat16 pWo1_h[1024*1024],    pWo1_l[1024*1024];
__device__ __nv_bfloat16 pWo2_h[1024*512],     pWo2_l[1024*512];
__device__ __nv_bfloat16 pWr1_h[300*1024],     pWr1_l[300*1024];
__device__ __nv_bfloat16 pWr2_h[1024*512],     pWr2_l[1024*512];
__device__ __nv_bfloat16 pWqkv_h[512*1536],    pWqkv_l[512*1536];
__device__ __nv_bfloat16 pWp_h [512*512],      pWp_l [512*512];
__device__ __nv_bfloat16 pWe_h [1024*512],     pWe_l [1024*512];
__device__ __nv_bfloat16 pT1_h [4096*1024],    pT1_l [4096*1024];
__device__ __nv_bfloat16 pH1o_h[4096*1024],    pH1o_l[4096*1024];
__device__ __nv_bfloat16 pT2_h [4096*512],     pT2_l [4096*512];
__device__ __nv_bfloat16 pZ_h  [16384*304],    pZ_l  [16384*304];   // ld=304
__device__ __nv_bfloat16 pH1r_h[16384*1024],   pH1r_l[16384*1024];
__device__ __nv_bfloat16 pT4_h [16384*512],    pT4_l [16384*512];
__device__ __nv_bfloat16 pGr_h [16384*512],    pGr_l [16384*512];
__device__ __nv_bfloat16 pOm_h [4096*512],     pOm_l [4096*512];
__device__ __nv_bfloat16 pCat_h[4096*1024],    pCat_l[4096*1024];

// ---------------------------------------------------------------------------
// helpers
// ---------------------------------------------------------------------------
__device__ __forceinline__ uint32_t smem_u32(const void* p) {
    uint32_t a;
    asm("{ .reg .u64 t; cvta.to.shared.u64 t, %1; cvt.u32.u64 %0, t; }"
        : "=r"(a) : "l"(p));
    return a;
}
__device__ __forceinline__ void cp16(uint32_t dst, const void* src, int sz) {
    asm volatile("cp.async.cg.shared.global [%0], [%1], 16, %2;"
                 :: "r"(dst), "l"(src), "r"(sz));
}
__device__ __forceinline__ void cp_commit() {
    asm volatile("cp.async.commit_group;");
}
__device__ __forceinline__ void cp_wait(int pend) {
    if (pend >= 1) asm volatile("cp.async.wait_group 1;");
    else           asm volatile("cp.async.wait_group 0;");
}
__device__ __forceinline__ void ldsm4(uint32_t* r, uint32_t addr) {
    asm volatile("ldmatrix.sync.aligned.m8n8.x4.shared.b16 {%0,%1,%2,%3}, [%4];"
                 : "=r"(r[0]), "=r"(r[1]), "=r"(r[2]), "=r"(r[3]) : "r"(addr));
}
__device__ __forceinline__ void ldsm4t(uint32_t* r, uint32_t addr) {
    asm volatile("ldmatrix.sync.aligned.m8n8.x4.trans.shared.b16 {%0,%1,%2,%3}, [%4];"
                 : "=r"(r[0]), "=r"(r[1]), "=r"(r[2]), "=r"(r[3]) : "r"(addr));
}
__device__ __forceinline__ void mma16816(float* d, const uint32_t* a, const uint32_t* b) {
    asm volatile(
        "mma.sync.aligned.m16n8k16.row.col.f32.bf16.bf16.f32 "
        "{%0,%1,%2,%3}, {%4,%5,%6,%7}, {%8,%9}, {%0,%1,%2,%3};"
        : "+f"(d[0]), "+f"(d[1]), "+f"(d[2]), "+f"(d[3])
        : "r"(a[0]), "r"(a[1]), "r"(a[2]), "r"(a[3]), "r"(b[0]), "r"(b[1]));
}
__device__ __forceinline__ void split1(float x, __nv_bfloat16& h, __nv_bfloat16& l) {
    h = __float2bfloat16(x);
    l = __float2bfloat16(x - __bfloat162float(h));
}

// ---------------------------------------------------------------------------
// SMEM stage layout (bytes)
// ---------------------------------------------------------------------------
#define PITCH_A 80
#define PITCH_B 272
#define OFF_AL 10240
#define OFF_BH 20480
#define OFF_BL 29184
#define STAGE_B 37888
#define NSTAGE 3
#define SMEM_DYN (NSTAGE * STAGE_B)     // 113664 -> 2 CTAs/SM

// ---------------------------------------------------------------------------
// GEMM descriptor (passed by value; two per launch -> merged grids)
// ---------------------------------------------------------------------------
struct GDesc {
    const __nv_bfloat16 *Ah, *Al, *Bh, *Bl;
    const float *bias, *X;
    float* Cf;
    __nv_bfloat16 *Ch, *Cl;
    long sAp, sBp, sX, sCf, sCo;
    int lda, ldb, ldo;
    int M, N, K, relu, rowmap;
    int gx, gy;
};

// ---------------------------------------------------------------------------
// HMMA bf16-split GEMM v5: merged dual-descriptor grid, 128 threads/CTA,
// 128x128 tile, 3-stage cp.async pipeline, 2 CTAs/SM.
// ---------------------------------------------------------------------------
__global__ __launch_bounds__(128, 2)
void mm2_kernel(GDesc d0, GDesc d1, int boundary)
{
    extern __shared__ char smem[];
    const uint32_t sbase = smem_u32(smem);

    const bool second = ((int)blockIdx.x >= boundary);
    const GDesc& d = second ? d1 : d0;
    const int local = (int)blockIdx.x - (second ? boundary : 0);
    const int gxy = d.gx * d.gy;
    const int bz  = local / gxy;
    const int rem = local - bz * gxy;
    const int by  = rem / d.gx;
    const int bxx = rem - by * d.gx;

    const __nv_bfloat16* Ah = d.Ah + (long)bz * d.sAp;
    const __nv_bfloat16* Al = d.Al + (long)bz * d.sAp;
    const __nv_bfloat16* Bh = d.Bh + (long)bz * d.sBp;
    const __nv_bfloat16* Bl = d.Bl + (long)bz * d.sBp;
    float* Cf = d.Cf ? (d.Cf + (long)bz * d.sCf) : nullptr;
    __nv_bfloat16* Ch = d.Ch ? (d.Ch + (long)bz * d.sCo) : nullptr;
    __nv_bfloat16* Cl = d.Cl ? (d.Cl + (long)bz * d.sCo) : nullptr;
    const float* X = d.X ? (d.X + (long)bz * d.sX) : nullptr;
    const int lda = d.lda, ldb = d.ldb, N = d.N, K = d.K;

    const int tid  = threadIdx.x;        // 0..127
    const int wid  = tid >> 5;
    const int lane = tid & 31;
    const int row0 = by * 128;
    const int col0 = bxx * 128;
    const int wm = wid >> 1;
    const int wn = wid & 1;

    float acc[4][8][4];
    #pragma unroll
    for (int mt = 0; mt < 4; ++mt)
        #pragma unroll
        for (int nt = 0; nt < 8; ++nt)
            #pragma unroll
            for (int e = 0; e < 4; ++e) acc[mt][nt][e] = 0.f;

    const int nch = (K + 31) >> 5;

    auto issueStage = [&](int c, int buf) {
        const int k0 = c << 5;
        const uint32_t sb = sbase + buf * STAGE_B;
        #pragma unroll
        for (int i = 0; i < 4; ++i) {
            const int ch  = tid + i * 128;
            const int row = ch >> 2;
            const int o8  = (ch & 3) * 8;
            const int rem2 = K - (k0 + o8);
            const int sz  = rem2 >= 8 ? 16 : (rem2 > 0 ? rem2 * 2 : 0);
            const long so = (long)(row0 + row) * lda + (sz ? (k0 + o8) : 0);
            const uint32_t dst = sb + row * PITCH_A + (ch & 3) * 16;
            cp16(dst,          Ah + so, sz);
            cp16(dst + OFF_AL, Al + so, sz);
        }
        #pragma unroll
        for (int i = 0; i < 4; ++i) {
            const int ch   = tid + i * 128;
            const int krow = ch >> 4;
            const int no8  = (ch & 15) * 8;
            const int remn = N - (col0 + no8);
            int sz = (k0 + krow < K) ? (remn >= 8 ? 16 : (remn > 0 ? remn * 2 : 0)) : 0;
            const long so = sz ? ((long)(k0 + krow) * ldb + col0 + no8) : 0;
            const uint32_t dst = sb + OFF_BH + krow * PITCH_B + (ch & 15) * 16;
            cp16(dst,                     Bh + so, sz);
            cp16(dst + (OFF_BL - OFF_BH), Bl + so, sz);
        }
    };

    auto computeChunk = [&](int buf) {
        const uint32_t sb = sbase + buf * STAGE_B;
        #pragma unroll
        for (int kb = 0; kb < 32; kb += 16) {
            uint32_t ahf[4][4], alf[4][4], bhf[8][2], blf[8][2];
            #pragma unroll
            for (int mt = 0; mt < 4; ++mt) {
                const uint32_t arow = wm * 64 + mt * 16 + (lane & 15);
                const uint32_t aoff = sb + arow * PITCH_A + (kb + ((lane >> 4) * 8)) * 2;
                ldsm4(ahf[mt], aoff);
                ldsm4(alf[mt], aoff + OFF_AL);
            }
            #pragma unroll
            for (int pair = 0; pair < 4; ++pair) {
                const uint32_t krow = kb + ((lane >> 3) & 1) * 8 + (lane & 7);
                const uint32_t ncol = wn * 64 + pair * 16 + (lane >> 4) * 8;
                const uint32_t boff = sb + OFF_BH + krow * PITCH_B + ncol * 2;
                uint32_t r4[4];
                ldsm4t(r4, boff);
                bhf[pair * 2][0] = r4[0]; bhf[pair * 2][1] = r4[1];
                bhf[pair * 2 + 1][0] = r4[2]; bhf[pair * 2 + 1][1] = r4[3];
                ldsm4t(r4, boff + (OFF_BL - OFF_BH));
                blf[pair * 2][0] = r4[0]; blf[pair * 2][1] = r4[1];
                blf[pair * 2 + 1][0] = r4[2]; blf[pair * 2 + 1][1] = r4[3];
            }
            #pragma unroll
            for (int mt = 0; mt < 4; ++mt)
                #pragma unroll
                for (int nt = 0; nt < 8; ++nt)
                    mma16816(acc[mt][nt], ahf[mt], bhf[nt]);
            #pragma unroll
            for (int mt = 0; mt < 4; ++mt)
                #pragma unroll
                for (int nt = 0; nt < 8; ++nt)
                    mma16816(acc[mt][nt], alf[mt], bhf[nt]);
            #pragma unroll
            for (int mt = 0; mt < 4; ++mt)
                #pragma unroll
                for (int nt = 0; nt < 8; ++nt)
                    mma16816(acc[mt][nt], ahf[mt], blf[nt]);
        }
    };

    issueStage(0, 0); cp_commit();
    if (nch > 1) { issueStage(1, 1); cp_commit(); }

    for (int c = 0; c < nch; ++c) {
        cp_wait((c + 2 <= nch) ? ((c + 1 < nch) ? 1 : 0) : 0);
        __syncthreads();
        if (c + 2 < nch) { issueStage(c + 2, (c + 2) % NSTAGE); cp_commit(); }
        computeChunk(c % NSTAGE);
    }

    // epilogue
    #pragma unroll
    for (int mt = 0; mt < 4; ++mt) {
        #pragma unroll
        for (int nt = 0; nt < 8; ++nt) {
            const int col = col0 + wn * 64 + nt * 8 + (lane & 3) * 2;
            if (col >= N) continue;
            #pragma unroll
            for (int half = 0; half < 2; ++half) {
                const int row = row0 + wm * 64 + mt * 16 + (lane >> 2) + half * 8;
                float2 v = make_float2(acc[mt][nt][half * 2], acc[mt][nt][half * 2 + 1]);
                if (d.bias) {
                    const float2 bv = *(const float2*)(d.bias + col);
                    v.x += bv.x; v.y += bv.y;
                }
                if (X) {
                    const float2 xv = *(const float2*)(X + (long)row * N + col);
                    v.x += xv.x; v.y += xv.y;
                }
                if (d.relu) { v.x = fmaxf(v.x, 0.f); v.y = fmaxf(v.y, 0.f); }
                int orow = row;
                if (d.rowmap) {
                    if (row < 2048) orow = ((row >> 3) << 4) + (row & 7);
                    else { const int a = row - 2048; orow = ((a >> 3) << 4) + 8 + (a & 7); }
                }
                if (Cf) *(float2*)(Cf + (long)orow * N + col) = v;
                if (Ch) {
                    __nv_bfloat16 hx, lx, hy, ly;
                    split1(v.x, hx, lx); split1(v.y, hy, ly);
                    const long o = (long)orow * d.ldo + col;
                    *(uint32_t*)(Ch + o) =
                        (uint32_t)__bfloat16_as_ushort(hx) | ((uint32_t)__bfloat16_as_ushort(hy) << 16);
                    *(uint32_t*)(Cl + o) =
                        (uint32_t)__bfloat16_as_ushort(lx) | ((uint32_t)__bfloat16_as_ushort(ly) << 16);
                }
            }
        }
    }
}

// ---------------------------------------------------------------------------
// Multi-job fp32 -> bf16 hi/lo plane convert (all inputs/weights, one launch)
// ---------------------------------------------------------------------------
#define NCVT 10
struct CvtJobs {
    const float* in[NCVT];
    __nv_bfloat16* h[NCVT];
    __nv_bfloat16* l[NCVT];
    long n[NCVT];
    int cols[NCVT], ldo[NCVT];
    int start[NCVT + 1];
};

__global__ __launch_bounds__(256)
void cvt_multi_kernel(CvtJobs J)
{
    const int bx = blockIdx.x;
    int j = 0;
    #pragma unroll
    for (int t = 0; t < NCVT - 1; ++t) if (bx >= J.start[t + 1]) j = t + 1;
    const long i = ((long)(bx - J.start[j]) * 256 + threadIdx.x) * 4;
    if (i >= J.n[j]) return;
    const float4 v = *(const float4*)(J.in[j] + i);
    long o;
    const int cols = J.cols[j], ldo = J.ldo[j];
    if (cols == ldo) o = i;
    else { const long r = i / cols; o = r * ldo + (int)(i - r * cols); }
    __nv_bfloat16 hh[4], ll[4];
    split1(v.x, hh[0], ll[0]); split1(v.y, hh[1], ll[1]);
    split1(v.z, hh[2], ll[2]); split1(v.w, hh[3], ll[3]);
    *(uint2*)(J.h[j] + o) = *(uint2*)hh;
    *(uint2*)(J.l[j] + o) = *(uint2*)ll;
}

__global__ __launch_bounds__(256)
void pack_qkv_kernel(const float* __restrict__ Wq, const float* __restrict__ Wk,
                     const float* __restrict__ Wv, const float* __restrict__ bq,
                     const float* __restrict__ bk, const float* __restrict__ bv,
                     __nv_bfloat16* __restrict__ h, __nv_bfloat16* __restrict__ l,
                     float* __restrict__ bias)
{
    const int idx = blockIdx.x * 256 + threadIdx.x;
    if (idx < 512 * 1536) {
        const int k = idx / 1536, n = idx % 1536, sel = n >> 9;
        const float* W = (sel == 0) ? Wq : (sel == 1) ? Wk : Wv;
        const float v = W[k * 512 + (n & 511)];
        __nv_bfloat16 hh, ll; split1(v, hh, ll);
        h[idx] = hh; l[idx] = ll;
    }
    if (idx < 1536) {
        const int sel = idx >> 9;
        const float* bb = (sel == 0) ? bq : (sel == 1) ? bk : bv;
        bias[idx] = bb[idx & 511];
    }
}

// ---------------------------------------------------------------------------
// Segmented MHA, both paths in one launch (blockIdx.z = path)
// ---------------------------------------------------------------------------
__global__ __launch_bounds__(128)
void attn_mean_kernel(const float* __restrict__ QKV,
                      __nv_bfloat16* __restrict__ OmH, __nv_bfloat16* __restrict__ OmL)
{
    const int s = blockIdx.x, h = blockIdx.y, path = blockIdx.z, tid = threadIdx.x;
    __shared__ float qs[8][DH_ + 1], ks[8][DH_ + 1], vs[8][DH_ + 1];
    __shared__ float sc[8][9], wj[8];

    #pragma unroll
    for (int i = 0; i < 8; ++i) {
        int g;
        if (path == 0) g = s * 8 + i;
        else { const int t = s >> 3, j = s & 7; g = t * 64 + i * 8 + j; }
        const long off = (long)g * 1536 + h * DH_ + tid;
        qs[i][tid] = QKV[off];
        ks[i][tid] = QKV[off + 512];
        vs[i][tid] = QKV[off + 1024];
    }
    __syncthreads();

    if (tid < 64) {
        const int i = tid >> 3, j = tid & 7;
        float d = 0.f;
        #pragma unroll 16
        for (int k = 0; k < DH_; ++k) d = fmaf(qs[i][k], ks[j][k], d);
        sc[i][j] = d * 0.08838834764831845f;
    }
    __syncthreads();
    if (tid < 8) {
        const int i = tid;
        float m = -1e30f;
        #pragma unroll
        for (int j = 0; j < 8; ++j) m = fmaxf(m, sc[i][j]);
        float e[8], sum = 0.f;
        #pragma unroll
        for (int j = 0; j < 8; ++j) { e[j] = __expf(sc[i][j] - m); sum += e[j]; }
        const float inv = 1.f / sum;
        #pragma unroll
        for (int j = 0; j < 8; ++j) sc[i][j] = e[j] * inv;
    }
    __syncthreads();
    if (tid < 8) {
        const int j = tid;
        float w = 0.f;
        #pragma unroll
        for (int i = 0; i < 8; ++i) w += sc[i][j];
        wj[j] = w * 0.125f;
    }
    __syncthreads();
    float o = 0.f;
    #pragma unroll
    for (int j = 0; j < 8; ++j) o = fmaf(wj[j], vs[j][tid], o);

    const long off = (long)(path * SEGS + s) * 512 + h * DH_ + tid;
    __nv_bfloat16 hh, ll; split1(o, hh, ll);
    OmH[off] = hh; OmL[off] = ll;
}

// ---------------------------------------------------------------------------
// Host
// ---------------------------------------------------------------------------
#define SYM(p, s) cudaGetSymbolAddress((void**)&p, s)

struct Planes { __nv_bfloat16 *h, *l; };

static GDesc mkDesc(Planes A, int lda, long sAp, Planes Bp, int ldb, long sBp,
                    const float* bias, const float* X, long sX,
                    float* Cf, long sCf, Planes Co, int ldo, long sCo,
                    int M, int N, int K, int nb, int relu, int rowmap,
                    int* ctas)
{
    GDesc d;
    d.Ah = A.h; d.Al = A.l; d.Bh = Bp.h; d.Bl = Bp.l;
    d.bias = bias; d.X = X; d.Cf = Cf; d.Ch = Co.h; d.Cl = Co.l;
    d.sAp = sAp; d.sBp = sBp; d.sX = sX; d.sCf = sCf; d.sCo = sCo;
    d.lda = lda; d.ldb = ldb; d.ldo = ldo;
    d.M = M; d.N = N; d.K = K; d.relu = relu; d.rowmap = rowmap;
    d.gx = (N + 127) / 128; d.gy = M / 128;
    *ctas = d.gx * d.gy * nb;
    return d;
}

static inline void launchPair(const GDesc& a, int ca, const GDesc& b, int cb)
{
    mm2_kernel<<<ca + cb, 128, SMEM_DYN>>>(a, b, ca);
}
static inline void launchOne(const GDesc& a, int ca)
{
    mm2_kernel<<<ca, 128, SMEM_DYN>>>(a, a, ca);
}

extern "C" void kernel_launch(void* const* d_in, const int* in_sizes, int n_in,
                              void* d_out, int out_size)
{
    const float* Ao   = (const float*)d_in[0];
    const float* srco = (const float*)d_in[1];
    const float* Ar   = (const float*)d_in[2];
    const float* srcr = (const float*)d_in[3];
    const float* Wo1  = (const float*)d_in[4];
    const float* Wo2  = (const float*)d_in[5];
    const float* Wr1  = (const float*)d_in[6];
    const float* Wr2  = (const float*)d_in[7];
    const float* Wq   = (const float*)d_in[8];
    const float* bq   = (const float*)d_in[9];
    const float* Wk   = (const float*)d_in[10];
    const float* bk   = (const float*)d_in[11];
    const float* Wv   = (const float*)d_in[12];
    const float* bv   = (const float*)d_in[13];
    const float* Wp   = (const float*)d_in[14];
    const float* bp   = (const float*)d_in[15];
    const float* We   = (const float*)d_in[16];
    const float* be   = (const float*)d_in[17];
    float* out = (float*)d_out;

    cudaFuncSetAttribute(mm2_kernel, cudaFuncAttributeMaxDynamicSharedMemorySize, SMEM_DYN);

    float *T1, *T2, *T4, *QKV, *bqkv;
    SYM(T1, g_T1); SYM(T2, g_T2); SYM(T4, g_T4);
    SYM(QKV, g_QKV); SYM(bqkv, g_bqkv);

    Planes PAo, PAr, PSo, PSr, PWo1, PWo2, PWr1, PWr2, PWqkv, PWp, PWe;
    Planes PT1, PH1o, PT2, PZ, PH1r, PT4, PGr, POm, PCat;
    SYM(PAo.h, pAo_h);   SYM(PAo.l, pAo_l);
    SYM(PAr.h, pAr_h);   SYM(PAr.l, pAr_l);
    SYM(PSo.h, pSo_h);   SYM(PSo.l, pSo_l);
    SYM(PSr.h, pSr_h);   SYM(PSr.l, pSr_l);
    SYM(PWo1.h, pWo1_h); SYM(PWo1.l, pWo1_l);
    SYM(PWo2.h, pWo2_h); SYM(PWo2.l, pWo2_l);
    SYM(PWr1.h, pWr1_h); SYM(PWr1.l, pWr1_l);
    SYM(PWr2.h, pWr2_h); SYM(PWr2.l, pWr2_l);
    SYM(PWqkv.h, pWqkv_h); SYM(PWqkv.l, pWqkv_l);
    SYM(PWp.h, pWp_h);   SYM(PWp.l, pWp_l);
    SYM(PWe.h, pWe_h);   SYM(PWe.l, pWe_l);
    SYM(PT1.h, pT1_h);   SYM(PT1.l, pT1_l);
    SYM(PH1o.h, pH1o_h); SYM(PH1o.l, pH1o_l);
    SYM(PT2.h, pT2_h);   SYM(PT2.l, pT2_l);
    SYM(PZ.h, pZ_h);     SYM(PZ.l, pZ_l);
    SYM(PH1r.h, pH1r_h); SYM(PH1r.l, pH1r_l);
    SYM(PT4.h, pT4_h);   SYM(PT4.l, pT4_l);
    SYM(PGr.h, pGr_h);   SYM(PGr.l, pGr_l);
    SYM(POm.h, pOm_h);   SYM(POm.l, pOm_l);
    SYM(PCat.h, pCat_h); SYM(PCat.l, pCat_l);

    const Planes NONE = {nullptr, nullptr};
    Planes PCatR = {PCat.h + 512, PCat.l + 512};   // right half of cat

    // ---- one merged conversion launch ----
    {
        CvtJobs J;
        const float* ins[NCVT] = {Ar, srcr, srco, Ao, Wo1, Wo2, Wr1, Wr2, Wp, We};
        Planes      ps [NCVT] = {PAr, PSr, PSo, PAo, PWo1, PWo2, PWr1, PWr2, PWp, PWe};
        long        ns [NCVT] = {(long)8*2048*2048, (long)16384*300, (long)4096*1024,
                                 (long)8*512*512, (long)1024*1024, (long)1024*512,
                                 (long)300*1024, (long)1024*512, (long)512*512,
                                 (long)1024*512};
        int         cs [NCVT] = {2048, 300, 1024, 512, 1024, 512, 1024, 512, 512, 512};
        int         ld [NCVT] = {2048, 304, 1024, 512, 1024, 512, 1024, 512, 512, 512};
        int cum = 0;
        for (int j = 0; j < NCVT; ++j) {
            J.in[j] = ins[j]; J.h[j] = ps[j].h; J.l[j] = ps[j].l;
            J.n[j] = ns[j]; J.cols[j] = cs[j]; J.ldo[j] = ld[j];
            J.start[j] = cum;
            cum += (int)((ns[j] + 1023) / 1024);
        }
        J.start[NCVT] = cum;
        cvt_multi_kernel<<<cum, 256>>>(J);
    }
    pack_qkv_kernel<<<(512 * 1536 + 255) / 256, 256>>>(Wq, Wk, Wv, bq, bk, bv,
                                                       PWqkv.h, PWqkv.l, bqkv);

    int c0, c1;
    // ---- pair 1: Z = Ar@srcr + srcr  ||  T1 = srco@Wo1 ----
    {
        GDesc dZ = mkDesc(PAr, 2048, (long)2048*2048, PSr, 304, (long)2048*304,
                          nullptr, srcr, (long)2048*300, nullptr, 0,
                          PZ, 304, (long)2048*304, 2048, 300, 2048, B_, 0, 0, &c0);
        GDesc dT1 = mkDesc(PSo, 1024, 0, PWo1, 1024, 0, nullptr, nullptr, 0,
                           T1, 0, PT1, 1024, 0, ROWS_O, 1024, 1024, 1, 0, 0, &c1);
        launchPair(dZ, c0, dT1, c1);
    }
    // ---- pair 2: H1r = relu(Z@Wr1)  ||  H1o = relu(Ao@T1 + T1) ----
    {
        GDesc dH1r = mkDesc(PZ, 304, 0, PWr1, 1024, 0, nullptr, nullptr, 0,
                            nullptr, 0, PH1r, 1024, 0, TOK, 1024, 300, 1, 1, 0, &c0);
        GDesc dH1o = mkDesc(PAo, 512, (long)512*512, PT1, 1024, (long)512*1024,
                            nullptr, T1, (long)512*1024, nullptr, 0,
                            PH1o, 1024, (long)512*1024, 512, 1024, 512, B_, 1, 0, &c1);
        launchPair(dH1r, c0, dH1o, c1);
    }
    // ---- pair 3: T4 = H1r@Wr2  ||  T2 = H1o@Wo2 ----
    {
        GDesc dT4 = mkDesc(PH1r, 1024, 0, PWr2, 512, 0, nullptr, nullptr, 0,
                           T4, 0, PT4, 512, 0, TOK, 512, 1024, 1, 0, 0, &c0);
        GDesc dT2 = mkDesc(PH1o, 1024, 0, PWo2, 512, 0, nullptr, nullptr, 0,
                           T2, 0, PT2, 512, 0, ROWS_O, 512, 1024, 1, 0, 0, &c1);
        launchPair(dT4, c0, dT2, c1);
    }
    // ---- pair 4: Gr = relu(Ar@T4 + T4)  ||  Go -> cat right half ----
    {
        GDesc dGr = mkDesc(PAr, 2048, (long)2048*2048, PT4, 512, (long)2048*512,
                           nullptr, T4, (long)2048*512, nullptr, 0,
                           PGr, 512, (long)2048*512, 2048, 512, 2048, B_, 1, 0, &c0);
        GDesc dGo = mkDesc(PAo, 512, (long)512*512, PT2, 512, (long)512*512,
                           nullptr, T2, (long)512*512, nullptr, 0,
                           PCatR, 1024, (long)512*1024, 512, 512, 512, B_, 1, 0, &c1);
        launchPair(dGr, c0, dGo, c1);
    }
    // ---- QKV (N=1536) ----
    {
        GDesc dQKV = mkDesc(PGr, 512, 0, PWqkv, 1536, 0, bqkv, nullptr, 0,
                            QKV, 0, NONE, 0, 0, TOK, 1536, 512, 1, 0, 0, &c0);
        launchOne(dQKV, c0);
    }
    // ---- attention ----
    {
        dim3 grid(SEGS, H_, 2);
        attn_mean_kernel<<<grid, 128>>>(QKV, POm.h, POm.l);
    }
    // ---- Wp projection -> cat left half (row-permuted) ----
    {
        GDesc dWp = mkDesc(POm, 512, 0, PWp, 512, 0, bp, nullptr, 0,
                           nullptr, 0, PCat, 1024, 0, 4096, 512, 512, 1, 0, 1, &c0);
        launchOne(dWp, c0);
    }
    // ---- final projection ----
    {
        GDesc dF = mkDesc(PCat, 1024, 0, PWe, 512, 0, be, nullptr, 0,
                          out, 0, NONE, 0, 0, OUT_ROWS, 512, 1024, 1, 0, 0, &c0);
        launchOne(dF, c0);
    }
}